// round 4
// baseline (speedup 1.0000x reference)
#include <cuda_runtime.h>
#include <cstdint>

#define F_IN  512
#define F_OUT 256
#define MAX_N 100000

// Scratch for the dense projection X @ W  (102.4 MB, __device__ global = allowed scratch)
__device__ float g_support[(size_t)MAX_N * F_OUT];

// ---------------------------------------------------------------------------
// Kernel 1: SGEMM  support[N,256] = X[N,512] @ W[512,256]   (fp32)
// BM=128, BN=128, BK=16, 256 threads, 8x8 per-thread microtile
// ---------------------------------------------------------------------------
#define BM 128
#define BN 128
#define BK 16
#define TM 8
#define TN 8

__global__ __launch_bounds__(256, 2)
void gcn_sgemm_kernel(const float* __restrict__ A,   // [N, 512]
                      const float* __restrict__ B,   // [512, 256]
                      float* __restrict__ C,         // [N, 256]
                      int N) {
    __shared__ float As[BK][BM + 4];   // A stored transposed, padded vs STS conflicts
    __shared__ float Bs[BK][BN];

    const int tid = threadIdx.x;
    const int bm = blockIdx.y * BM;
    const int bn = blockIdx.x * BN;

    // A tile load mapping: 128 rows x 16 cols, each thread 2 x float4
    const int aRow = tid >> 2;          // 0..63
    const int aCol = (tid & 3) << 2;    // 0,4,8,12
    // B tile load mapping: 16 rows x 128 cols, each thread 2 x float4
    const int bRow = tid >> 5;          // 0..7
    const int bCol = (tid & 31) << 2;   // 0..124

    const int ty = tid >> 4;            // 0..15 (row group)
    const int tx = tid & 15;            // 0..15 (col group)

    float acc[TM][TN];
    #pragma unroll
    for (int i = 0; i < TM; i++)
        #pragma unroll
        for (int j = 0; j < TN; j++) acc[i][j] = 0.0f;

    float regM[TM], regN[TN];

    for (int k0 = 0; k0 < F_IN; k0 += BK) {
        // --- load A tile (transposed into As) ---
        #pragma unroll
        for (int i = 0; i < 2; i++) {
            int r = aRow + i * 64;
            int grow = bm + r;
            float4 v = make_float4(0.f, 0.f, 0.f, 0.f);
            if (grow < N)
                v = *(const float4*)(A + (size_t)grow * F_IN + k0 + aCol);
            As[aCol + 0][r] = v.x;
            As[aCol + 1][r] = v.y;
            As[aCol + 2][r] = v.z;
            As[aCol + 3][r] = v.w;
        }
        // --- load B tile ---
        #pragma unroll
        for (int i = 0; i < 2; i++) {
            int r = bRow + i * 8;
            *(float4*)&Bs[r][bCol] =
                *(const float4*)(B + (size_t)(k0 + r) * F_OUT + bn + bCol);
        }
        __syncthreads();

        #pragma unroll
        for (int k = 0; k < BK; k++) {
            #pragma unroll
            for (int i = 0; i < TM; i++) regM[i] = As[k][ty * TM + i];
            #pragma unroll
            for (int j = 0; j < TN; j++) regN[j] = Bs[k][tx * TN + j];
            #pragma unroll
            for (int i = 0; i < TM; i++)
                #pragma unroll
                for (int j = 0; j < TN; j++)
                    acc[i][j] += regM[i] * regN[j];
        }
        __syncthreads();
    }

    // --- store C ---
    #pragma unroll
    for (int i = 0; i < TM; i++) {
        int grow = bm + ty * TM + i;
        if (grow < N) {
            #pragma unroll
            for (int j = 0; j < TN; j += 4) {
                float4 v = make_float4(acc[i][j], acc[i][j + 1],
                                       acc[i][j + 2], acc[i][j + 3]);
                *(float4*)(C + (size_t)grow * F_OUT + bn + tx * TN + j) = v;
            }
        }
    }
}

// ---------------------------------------------------------------------------
// Kernel 2: COO SpMM scatter  out[row[e]] += edge_val[e] * support[col[e]]
// One warp per edge; lane handles 2 float4 (2*4*32 = 256 floats = F_OUT).
// red.global.add.v4.f32 cuts REDG issue count 4x vs scalar atomicAdd.
// ---------------------------------------------------------------------------
__global__ __launch_bounds__(256)
void gcn_spmm_kernel(const float* __restrict__ support,
                     const float* __restrict__ edge_val,
                     const int* __restrict__ row,
                     const int* __restrict__ col,
                     float* __restrict__ out,
                     int E) {
    int warp = (blockIdx.x * blockDim.x + threadIdx.x) >> 5;
    int lane = threadIdx.x & 31;
    if (warp >= E) return;

    int r = __ldg(row + warp);
    int c = __ldg(col + warp);
    float w = __ldg(edge_val + warp);

    const float4* src = (const float4*)(support + (size_t)c * F_OUT);
    float* dst = out + (size_t)r * F_OUT;

    #pragma unroll
    for (int i = 0; i < 2; i++) {
        float4 v = __ldg(src + lane + i * 32);
        float mx = v.x * w, my = v.y * w, mz = v.z * w, mw = v.w * w;
        asm volatile("red.global.add.v4.f32 [%0], {%1, %2, %3, %4};"
                     :: "l"(dst + (size_t)(lane + i * 32) * 4),
                        "f"(mx), "f"(my), "f"(mz), "f"(mw)
                     : "memory");
    }
}

// ---------------------------------------------------------------------------
// Kernel 3: finalize  out = round_half_even(out*1000)/1000 + bias
// rintf == round-to-nearest-even == jnp.round; __fdiv_rn stays IEEE under fastmath
// ---------------------------------------------------------------------------
__global__ __launch_bounds__(256)
void gcn_finalize_kernel(float* __restrict__ out,
                         const float* __restrict__ bias,
                         int total) {
    int i4 = blockIdx.x * blockDim.x + threadIdx.x;
    if (i4 * 4 >= total) return;
    float4 v = *(float4*)(out + (size_t)i4 * 4);
    int b = (i4 * 4) & (F_OUT - 1);
    v.x = __fdiv_rn(rintf(v.x * 1000.0f), 1000.0f) + __ldg(bias + b + 0);
    v.y = __fdiv_rn(rintf(v.y * 1000.0f), 1000.0f) + __ldg(bias + b + 1);
    v.z = __fdiv_rn(rintf(v.z * 1000.0f), 1000.0f) + __ldg(bias + b + 2);
    v.w = __fdiv_rn(rintf(v.w * 1000.0f), 1000.0f) + __ldg(bias + b + 3);
    *(float4*)(out + (size_t)i4 * 4) = v;
}

// ---------------------------------------------------------------------------
// Launch. Inputs (metadata order):
//   0: input [N,512] f32   1: weight [512,256] f32   2: bias [256] f32
//   3: edge_val [E] f32    4: row [E] i32             5: col [E] i32
// Output: [N,256] f32
// ---------------------------------------------------------------------------
extern "C" void kernel_launch(void* const* d_in, const int* in_sizes, int n_in,
                              void* d_out, int out_size) {
    const float* x        = (const float*)d_in[0];
    const float* weight   = (const float*)d_in[1];
    const float* bias     = (const float*)d_in[2];
    const float* edge_val = (const float*)d_in[3];
    const int*   row      = (const int*)d_in[4];
    const int*   col      = (const int*)d_in[5];
    float*       out      = (float*)d_out;

    const int N = in_sizes[0] / F_IN;
    const int E = in_sizes[3];

    float* support;
    cudaGetSymbolAddress((void**)&support, g_support);

    // Zero the accumulation target (d_out is poisoned 0xAA each run)
    cudaMemsetAsync(d_out, 0, (size_t)out_size * sizeof(float), 0);

    // 1) support = X @ W
    dim3 gemm_grid(F_OUT / BN, (N + BM - 1) / BM);
    gcn_sgemm_kernel<<<gemm_grid, 256>>>(x, weight, support, N);

    // 2) scatter-add over edges (one warp per edge)
    int warps = E;
    int blocks = (warps * 32 + 255) / 256;
    gcn_spmm_kernel<<<blocks, 256>>>(support, edge_val, row, col, out, E);

    // 3) round + bias
    int total = out_size;
    int fblocks = (total / 4 + 255) / 256;
    gcn_finalize_kernel<<<fblocks, 256>>>(out, bias, total);
}

// round 5
// speedup vs baseline: 1.5365x; 1.5365x over previous
#include <cuda_runtime.h>
#include <cstdint>

#define F_IN  512
#define F_OUT 256
#define MAX_N 100000
#define MAX_E 3200000

// ---------------- device scratch (allowed: __device__ globals) --------------
__device__ float g_support[(size_t)MAX_N * F_OUT];          // X @ W   (102.4 MB)
__device__ int   g_count[MAX_N];                            // histogram
__device__ int   g_rowptr[MAX_N + 1];                       // CSR row pointers
__device__ int   g_wofs[MAX_N];                             // scatter cursors
__device__ int2  g_edges[MAX_E];                            // (col, val bits) sorted by row

// ---------------------------------------------------------------------------
// Kernel 1: SGEMM  support[N,256] = X[N,512] @ W[512,256]  (fp32, FFMA2 core)
// BM=128, BN=128, BK=16, 256 threads, 8x8 per-thread microtile
// ---------------------------------------------------------------------------
#define BM 128
#define BN 128
#define BK 16
#define TM 8
#define TN 8

__global__ __launch_bounds__(256, 2)
void gcn_sgemm_kernel(const float* __restrict__ A,   // [N, 512]
                      const float* __restrict__ B,   // [512, 256]
                      float* __restrict__ C,         // [N, 256]
                      int N) {
    __shared__ __align__(16) float As[BK][BM + 4];   // A transposed, padded
    __shared__ __align__(16) float Bs[BK][BN];

    const int tid = threadIdx.x;
    const int bm = blockIdx.y * BM;
    const int bn = blockIdx.x * BN;

    const int aRow = tid >> 2;          // 0..63
    const int aCol = (tid & 3) << 2;    // 0,4,8,12
    const int bRow = tid >> 5;          // 0..7
    const int bCol = (tid & 31) << 2;   // 0..124

    const int ty = tid >> 4;            // 0..15
    const int tx = tid & 15;            // 0..15

    // packed fp32x2 accumulators: acc2[i][jp] holds C cols (2*jp, 2*jp+1)
    unsigned long long acc2[TM][TN / 2];
    #pragma unroll
    for (int i = 0; i < TM; i++)
        #pragma unroll
        for (int jp = 0; jp < TN / 2; jp++) acc2[i][jp] = 0ULL;

    for (int k0 = 0; k0 < F_IN; k0 += BK) {
        #pragma unroll
        for (int i = 0; i < 2; i++) {
            int r = aRow + i * 64;
            int grow = bm + r;
            float4 v = make_float4(0.f, 0.f, 0.f, 0.f);
            if (grow < N)
                v = *(const float4*)(A + (size_t)grow * F_IN + k0 + aCol);
            As[aCol + 0][r] = v.x;
            As[aCol + 1][r] = v.y;
            As[aCol + 2][r] = v.z;
            As[aCol + 3][r] = v.w;
        }
        #pragma unroll
        for (int i = 0; i < 2; i++) {
            int r = bRow + i * 8;
            *(float4*)&Bs[r][bCol] =
                *(const float4*)(B + (size_t)(k0 + r) * F_OUT + bn + bCol);
        }
        __syncthreads();

        #pragma unroll
        for (int k = 0; k < BK; k++) {
            // N-fragment: 8 floats as 4 packed f32x2 (LDS.128 x2)
            const ulonglong2* bp = (const ulonglong2*)&Bs[k][tx * TN];
            ulonglong2 q0 = bp[0];
            ulonglong2 q1 = bp[1];
            unsigned long long nreg[4] = {q0.x, q0.y, q1.x, q1.y};

            // M-fragment: 8 floats (LDS.128 x2)
            float4 m0 = *(const float4*)&As[k][ty * TM];
            float4 m1 = *(const float4*)&As[k][ty * TM + 4];
            float regM[TM] = {m0.x, m0.y, m0.z, m0.w, m1.x, m1.y, m1.z, m1.w};

            #pragma unroll
            for (int i = 0; i < TM; i++) {
                unsigned long long m2;
                asm("mov.b64 %0, {%1, %1};" : "=l"(m2) : "f"(regM[i]));
                #pragma unroll
                for (int jp = 0; jp < TN / 2; jp++) {
                    asm("fma.rn.f32x2 %0, %1, %2, %0;"
                        : "+l"(acc2[i][jp]) : "l"(m2), "l"(nreg[jp]));
                }
            }
        }
        __syncthreads();
    }

    #pragma unroll
    for (int i = 0; i < TM; i++) {
        int grow = bm + ty * TM + i;
        if (grow < N) {
            float out8[TM];
            #pragma unroll
            for (int jp = 0; jp < TN / 2; jp++) {
                asm("mov.b64 {%0, %1}, %2;"
                    : "=f"(out8[2 * jp]), "=f"(out8[2 * jp + 1])
                    : "l"(acc2[i][jp]));
            }
            float* cp = C + (size_t)grow * F_OUT + bn + tx * TN;
            *(float4*)(cp + 0) = make_float4(out8[0], out8[1], out8[2], out8[3]);
            *(float4*)(cp + 4) = make_float4(out8[4], out8[5], out8[6], out8[7]);
        }
    }
}

// ---------------------------------------------------------------------------
// Kernel 2a: histogram of destination rows
// ---------------------------------------------------------------------------
__global__ __launch_bounds__(256)
void gcn_hist_kernel(const int* __restrict__ row, int E) {
    int e = blockIdx.x * blockDim.x + threadIdx.x;
    if (e < E) atomicAdd(&g_count[row[e]], 1);
}

// ---------------------------------------------------------------------------
// Kernel 2b: exclusive scan of counts -> rowptr (+ write cursors)
// Single block, 1024 threads, sequential 1024-chunks with running carry.
// ---------------------------------------------------------------------------
__global__ __launch_bounds__(1024)
void gcn_scan_kernel(int n) {
    __shared__ int warp_sums[32];
    __shared__ int s_carry;
    const int tid  = threadIdx.x;
    const int lane = tid & 31;
    const int wid  = tid >> 5;
    if (tid == 0) s_carry = 0;
    __syncthreads();

    for (int base = 0; base < n; base += 1024) {
        int i = base + tid;
        int v = (i < n) ? g_count[i] : 0;

        // warp inclusive scan
        int x = v;
        #pragma unroll
        for (int d = 1; d < 32; d <<= 1) {
            int y = __shfl_up_sync(0xffffffff, x, d);
            if (lane >= d) x += y;
        }
        if (lane == 31) warp_sums[wid] = x;
        __syncthreads();
        if (wid == 0) {
            int t = warp_sums[lane];
            #pragma unroll
            for (int d = 1; d < 32; d <<= 1) {
                int y = __shfl_up_sync(0xffffffff, t, d);
                if (lane >= d) t += y;
            }
            warp_sums[lane] = t;   // inclusive warp totals
        }
        __syncthreads();

        int warp_off = (wid > 0) ? warp_sums[wid - 1] : 0;
        int excl = s_carry + warp_off + x - v;
        if (i < n) { g_rowptr[i] = excl; g_wofs[i] = excl; }
        __syncthreads();                     // everyone read s_carry
        if (tid == 0) s_carry += warp_sums[31];
        __syncthreads();
    }
    if (threadIdx.x == 0) g_rowptr[n] = s_carry;
}

// ---------------------------------------------------------------------------
// Kernel 2c: scatter edges into row-sorted order
// ---------------------------------------------------------------------------
__global__ __launch_bounds__(256)
void gcn_scatter_kernel(const int* __restrict__ row,
                        const int* __restrict__ col,
                        const float* __restrict__ val, int E) {
    int e = blockIdx.x * blockDim.x + threadIdx.x;
    if (e >= E) return;
    int r = row[e];
    int p = atomicAdd(&g_wofs[r], 1);
    g_edges[p] = make_int2(col[e], __float_as_int(val[e]));
}

// ---------------------------------------------------------------------------
// Kernel 3: CSR segment reduction + fused round/bias epilogue
// One warp per output row; lane handles 8 floats (2 x float4).
// Single plain store per element — no atomics, no memset, no finalize pass.
// ---------------------------------------------------------------------------
__global__ __launch_bounds__(256)
void gcn_csr_kernel(const float* __restrict__ support,
                    const float* __restrict__ bias,
                    float* __restrict__ out, int N) {
    int w    = (blockIdx.x * blockDim.x + threadIdx.x) >> 5;
    int lane = threadIdx.x & 31;
    if (w >= N) return;

    int s = g_rowptr[w];
    int e = g_rowptr[w + 1];

    float4 acc0 = make_float4(0.f, 0.f, 0.f, 0.f);
    float4 acc1 = make_float4(0.f, 0.f, 0.f, 0.f);

    int i = s;
    for (; i + 2 <= e; i += 2) {                 // unroll x2 for MLP
        int2 cv0 = g_edges[i];
        int2 cv1 = g_edges[i + 1];
        float w0 = __int_as_float(cv0.y);
        float w1 = __int_as_float(cv1.y);
        const float4* s0 = (const float4*)(support + (size_t)cv0.x * F_OUT);
        const float4* s1 = (const float4*)(support + (size_t)cv1.x * F_OUT);
        float4 a0 = __ldg(s0 + lane),      b0 = __ldg(s0 + lane + 32);
        float4 a1 = __ldg(s1 + lane),      b1 = __ldg(s1 + lane + 32);
        acc0.x = fmaf(w0, a0.x, acc0.x);  acc0.y = fmaf(w0, a0.y, acc0.y);
        acc0.z = fmaf(w0, a0.z, acc0.z);  acc0.w = fmaf(w0, a0.w, acc0.w);
        acc1.x = fmaf(w0, b0.x, acc1.x);  acc1.y = fmaf(w0, b0.y, acc1.y);
        acc1.z = fmaf(w0, b0.z, acc1.z);  acc1.w = fmaf(w0, b0.w, acc1.w);
        acc0.x = fmaf(w1, a1.x, acc0.x);  acc0.y = fmaf(w1, a1.y, acc0.y);
        acc0.z = fmaf(w1, a1.z, acc0.z);  acc0.w = fmaf(w1, a1.w, acc0.w);
        acc1.x = fmaf(w1, b1.x, acc1.x);  acc1.y = fmaf(w1, b1.y, acc1.y);
        acc1.z = fmaf(w1, b1.z, acc1.z);  acc1.w = fmaf(w1, b1.w, acc1.w);
    }
    if (i < e) {
        int2 cv = g_edges[i];
        float w0 = __int_as_float(cv.y);
        const float4* s0 = (const float4*)(support + (size_t)cv.x * F_OUT);
        float4 a0 = __ldg(s0 + lane), b0 = __ldg(s0 + lane + 32);
        acc0.x = fmaf(w0, a0.x, acc0.x);  acc0.y = fmaf(w0, a0.y, acc0.y);
        acc0.z = fmaf(w0, a0.z, acc0.z);  acc0.w = fmaf(w0, a0.w, acc0.w);
        acc1.x = fmaf(w0, b0.x, acc1.x);  acc1.y = fmaf(w0, b0.y, acc1.y);
        acc1.z = fmaf(w0, b0.z, acc1.z);  acc1.w = fmaf(w0, b0.w, acc1.w);
    }

    // fused epilogue: round-half-even(x*1000)/1000 + bias
    float4 bi0 = __ldg((const float4*)bias + lane);
    float4 bi1 = __ldg((const float4*)bias + lane + 32);
    float4 o0, o1;
    o0.x = __fdiv_rn(rintf(acc0.x * 1000.0f), 1000.0f) + bi0.x;
    o0.y = __fdiv_rn(rintf(acc0.y * 1000.0f), 1000.0f) + bi0.y;
    o0.z = __fdiv_rn(rintf(acc0.z * 1000.0f), 1000.0f) + bi0.z;
    o0.w = __fdiv_rn(rintf(acc0.w * 1000.0f), 1000.0f) + bi0.w;
    o1.x = __fdiv_rn(rintf(acc1.x * 1000.0f), 1000.0f) + bi1.x;
    o1.y = __fdiv_rn(rintf(acc1.y * 1000.0f), 1000.0f) + bi1.y;
    o1.z = __fdiv_rn(rintf(acc1.z * 1000.0f), 1000.0f) + bi1.z;
    o1.w = __fdiv_rn(rintf(acc1.w * 1000.0f), 1000.0f) + bi1.w;

    float4* dst = (float4*)(out + (size_t)w * F_OUT);
    dst[lane]      = o0;
    dst[lane + 32] = o1;
}

// ---------------------------------------------------------------------------
// Launch. Inputs (metadata order):
//   0: input [N,512] f32   1: weight [512,256] f32   2: bias [256] f32
//   3: edge_val [E] f32    4: row [E] i32             5: col [E] i32
// Output: [N,256] f32
// ---------------------------------------------------------------------------
extern "C" void kernel_launch(void* const* d_in, const int* in_sizes, int n_in,
                              void* d_out, int out_size) {
    const float* x        = (const float*)d_in[0];
    const float* weight   = (const float*)d_in[1];
    const float* bias     = (const float*)d_in[2];
    const float* edge_val = (const float*)d_in[3];
    const int*   row      = (const int*)d_in[4];
    const int*   col      = (const int*)d_in[5];
    float*       out      = (float*)d_out;

    const int N = in_sizes[0] / F_IN;
    const int E = in_sizes[3];

    float* support;
    cudaGetSymbolAddress((void**)&support, g_support);
    int* count_ptr;
    cudaGetSymbolAddress((void**)&count_ptr, g_count);

    // zero the histogram (g_edges / rowptr / wofs are fully overwritten)
    cudaMemsetAsync(count_ptr, 0, (size_t)N * sizeof(int), 0);

    const int eblocks = (E + 255) / 256;

    // CSR build chain
    gcn_hist_kernel<<<eblocks, 256>>>(row, E);
    gcn_scan_kernel<<<1, 1024>>>(N);
    gcn_scatter_kernel<<<eblocks, 256>>>(row, col, edge_val, E);

    // dense projection
    dim3 gemm_grid(F_OUT / BN, (N + BM - 1) / BM);
    gcn_sgemm_kernel<<<gemm_grid, 256>>>(x, weight, support, N);

    // segment reduce + fused epilogue (warp per row)
    int csr_blocks = (N * 32 + 255) / 256;
    gcn_csr_kernel<<<csr_blocks, 256>>>(support, bias, out, N);
}

// round 7
// speedup vs baseline: 2.2827x; 1.4857x over previous
#include <cuda_runtime.h>
#include <cuda_bf16.h>
#include <cstdint>

#define F_IN  512
#define F_OUT 256
#define MAX_N 100000
#define MAX_E 3200000

// ---------------- device scratch -------------------------------------------
__device__ float g_support[(size_t)MAX_N * F_OUT];          // X @ W
__device__ int   g_count[MAX_N];
__device__ int   g_rowptr[MAX_N + 1];
__device__ int   g_wofs[MAX_N];
__device__ int2  g_edges[MAX_E];

// ---------------- PTX helpers ----------------------------------------------
__device__ __forceinline__ uint32_t smem_u32(const void* p) {
    uint32_t a;
    asm("{ .reg .u64 t; cvta.to.shared.u64 t, %1; cvt.u32.u64 %0, t; }"
        : "=r"(a) : "l"(p));
    return a;
}

#define LDSM_X4(r0, r1, r2, r3, addr) \
    asm volatile("ldmatrix.sync.aligned.m8n8.x4.shared.b16 {%0,%1,%2,%3}, [%4];" \
                 : "=r"(r0), "=r"(r1), "=r"(r2), "=r"(r3) : "r"(addr))

#define LDSM_X4_T(r0, r1, r2, r3, addr) \
    asm volatile("ldmatrix.sync.aligned.m8n8.x4.trans.shared.b16 {%0,%1,%2,%3}, [%4];" \
                 : "=r"(r0), "=r"(r1), "=r"(r2), "=r"(r3) : "r"(addr))

#define MMA_BF16(d0, d1, d2, d3, a0, a1, a2, a3, b0, b1) \
    asm volatile("mma.sync.aligned.m16n8k16.row.col.f32.bf16.bf16.f32 " \
                 "{%0,%1,%2,%3}, {%4,%5,%6,%7}, {%8,%9}, {%0,%1,%2,%3};" \
                 : "+f"(d0), "+f"(d1), "+f"(d2), "+f"(d3) \
                 : "r"(a0), "r"(a1), "r"(a2), "r"(a3), "r"(b0), "r"(b1))

// split fp32x4 -> (hi bf16x4, lo bf16x4) packed as uint2 each
__device__ __forceinline__ void split4(float4 v, uint2& h, uint2& l) {
    __nv_bfloat162 h01 = __float22bfloat162_rn(make_float2(v.x, v.y));
    __nv_bfloat162 h23 = __float22bfloat162_rn(make_float2(v.z, v.w));
    float2 f01 = __bfloat1622float2(h01);
    float2 f23 = __bfloat1622float2(h23);
    __nv_bfloat162 l01 = __float22bfloat162_rn(make_float2(v.x - f01.x, v.y - f01.y));
    __nv_bfloat162 l23 = __float22bfloat162_rn(make_float2(v.z - f23.x, v.w - f23.y));
    h.x = *(uint32_t*)&h01;  h.y = *(uint32_t*)&h23;
    l.x = *(uint32_t*)&l01;  l.y = *(uint32_t*)&l23;
}

// ---------------------------------------------------------------------------
// Kernel 1: split-bf16 HMMA GEMM  support[N,256] = X[N,512] @ W[512,256]
// CTA 128x128, 8 warps (4M x 2N), warp tile 32x64, K-tile 32.
// 3 MMAs per product: AhBh + AlBh + AhBl (fp32 accum), residual ~2^-16.
// ---------------------------------------------------------------------------
#define SA_STR 40     // A smem row stride (elems), 128 rows
#define SB_STR 136    // B smem row stride (elems), 32 k-rows

__global__ __launch_bounds__(256, 2)
void gcn_mma_gemm(const float* __restrict__ A,   // [N, 512]
                  const float* __restrict__ W,   // [512, 256]
                  float* __restrict__ C,         // [N, 256]
                  int Nn) {
    __shared__ __align__(16) __nv_bfloat16 sAh[128 * SA_STR];
    __shared__ __align__(16) __nv_bfloat16 sAl[128 * SA_STR];
    __shared__ __align__(16) __nv_bfloat16 sBh[32 * SB_STR];
    __shared__ __align__(16) __nv_bfloat16 sBl[32 * SB_STR];

    const int tid   = threadIdx.x;
    const int lane  = tid & 31;
    const int wid   = tid >> 5;
    const int warpM = wid & 3;      // 0..3 -> m offset 32*warpM
    const int warpN = wid >> 2;     // 0..1 -> n offset 64*warpN
    const int m0    = blockIdx.y * 128;
    const int n0    = blockIdx.x * 128;

    const uint32_t sAh_b = smem_u32(sAh);
    const uint32_t sAl_b = smem_u32(sAl);
    const uint32_t sBh_b = smem_u32(sBh);
    const uint32_t sBl_b = smem_u32(sBl);

    float acc[2][8][4];
    #pragma unroll
    for (int i = 0; i < 2; i++)
        #pragma unroll
        for (int j = 0; j < 8; j++)
            #pragma unroll
            for (int k = 0; k < 4; k++) acc[i][j][k] = 0.0f;

    // gmem->smem mappings
    const int ar = tid >> 1;               // A row 0..127
    const int ac = (tid & 1) * 16;         // A k offset 0/16
    const int kr = tid >> 3;               // B k-row 0..31
    const int nc = (tid & 7) * 16;         // B n offset 0..112

    // ldmatrix per-thread address components
    const uint32_t a_row  = (uint32_t)(warpM * 32 + (lane & 15));
    const uint32_t a_colb = (uint32_t)((lane >> 4) * 8);
    const uint32_t b_k    = (uint32_t)(((lane >> 3) & 1) * 8 + (lane & 7));
    const uint32_t b_n    = (uint32_t)(warpN * 64 + (lane >> 4) * 8);

    for (int kt = 0; kt < F_IN / 32; kt++) {
        const int k0 = kt * 32;

        // ---- load + split + STS ----
        {
            const int grow = m0 + ar;
            const float4* ap = (const float4*)(A + (size_t)grow * F_IN + k0 + ac);
            #pragma unroll
            for (int i = 0; i < 4; i++) {
                float4 v = (grow < Nn) ? __ldg(ap + i)
                                       : make_float4(0.f, 0.f, 0.f, 0.f);
                uint2 h, l;
                split4(v, h, l);
                *(uint2*)(sAh + ar * SA_STR + ac + i * 4) = h;
                *(uint2*)(sAl + ar * SA_STR + ac + i * 4) = l;
            }
            const float4* bp = (const float4*)(W + (size_t)(k0 + kr) * F_OUT + n0 + nc);
            #pragma unroll
            for (int i = 0; i < 4; i++) {
                float4 v = __ldg(bp + i);
                uint2 h, l;
                split4(v, h, l);
                *(uint2*)(sBh + kr * SB_STR + nc + i * 4) = h;
                *(uint2*)(sBl + kr * SB_STR + nc + i * 4) = l;
            }
        }
        __syncthreads();

        // ---- compute: 2 k16 steps x 3 split terms ----
        #pragma unroll
        for (int ks = 0; ks < 2; ks++) {
            const uint32_t aoff0 = (a_row * SA_STR + (uint32_t)(ks * 16) + a_colb) * 2;
            const uint32_t aoff1 = aoff0 + 16 * SA_STR * 2;
            const uint32_t boffk = ((b_k + (uint32_t)(ks * 16)) * SB_STR + b_n) * 2;

            uint32_t ah[8], al[8], b[16];

            // A-hi, B-hi
            LDSM_X4(ah[0], ah[1], ah[2], ah[3], sAh_b + aoff0);
            LDSM_X4(ah[4], ah[5], ah[6], ah[7], sAh_b + aoff1);
            #pragma unroll
            for (int lg = 0; lg < 4; lg++)
                LDSM_X4_T(b[4 * lg], b[4 * lg + 1], b[4 * lg + 2], b[4 * lg + 3],
                          sBh_b + boffk + (uint32_t)(lg * 16) * 2);

            #pragma unroll
            for (int mf = 0; mf < 2; mf++)
                #pragma unroll
                for (int nf = 0; nf < 8; nf++)
                    MMA_BF16(acc[mf][nf][0], acc[mf][nf][1], acc[mf][nf][2], acc[mf][nf][3],
                             ah[4 * mf], ah[4 * mf + 1], ah[4 * mf + 2], ah[4 * mf + 3],
                             b[2 * nf], b[2 * nf + 1]);

            // A-lo x B-hi
            LDSM_X4(al[0], al[1], al[2], al[3], sAl_b + aoff0);
            LDSM_X4(al[4], al[5], al[6], al[7], sAl_b + aoff1);
            #pragma unroll
            for (int mf = 0; mf < 2; mf++)
                #pragma unroll
                for (int nf = 0; nf < 8; nf++)
                    MMA_BF16(acc[mf][nf][0], acc[mf][nf][1], acc[mf][nf][2], acc[mf][nf][3],
                             al[4 * mf], al[4 * mf + 1], al[4 * mf + 2], al[4 * mf + 3],
                             b[2 * nf], b[2 * nf + 1]);

            // A-hi x B-lo
            #pragma unroll
            for (int lg = 0; lg < 4; lg++)
                LDSM_X4_T(b[4 * lg], b[4 * lg + 1], b[4 * lg + 2], b[4 * lg + 3],
                          sBl_b + boffk + (uint32_t)(lg * 16) * 2);
            #pragma unroll
            for (int mf = 0; mf < 2; mf++)
                #pragma unroll
                for (int nf = 0; nf < 8; nf++)
                    MMA_BF16(acc[mf][nf][0], acc[mf][nf][1], acc[mf][nf][2], acc[mf][nf][3],
                             ah[4 * mf], ah[4 * mf + 1], ah[4 * mf + 2], ah[4 * mf + 3],
                             b[2 * nf], b[2 * nf + 1]);
        }
        __syncthreads();
    }

    // ---- epilogue ----
    const int g  = lane >> 2;
    const int tg = lane & 3;
    #pragma unroll
    for (int mf = 0; mf < 2; mf++) {
        #pragma unroll
        for (int nf = 0; nf < 8; nf++) {
            const int col  = n0 + warpN * 64 + nf * 8 + tg * 2;
            const int row0 = m0 + warpM * 32 + mf * 16 + g;
            const int row1 = row0 + 8;
            if (row0 < Nn)
                *(float2*)(C + (size_t)row0 * F_OUT + col) =
                    make_float2(acc[mf][nf][0], acc[mf][nf][1]);
            if (row1 < Nn)
                *(float2*)(C + (size_t)row1 * F_OUT + col) =
                    make_float2(acc[mf][nf][2], acc[mf][nf][3]);
        }
    }
}

// ---------------------------------------------------------------------------
// Kernel 2a: histogram of destination rows
// ---------------------------------------------------------------------------
__global__ __launch_bounds__(256)
void gcn_hist_kernel(const int* __restrict__ row, int E) {
    int e = blockIdx.x * blockDim.x + threadIdx.x;
    if (e < E) atomicAdd(&g_count[row[e]], 1);
}

// ---------------------------------------------------------------------------
// Kernel 2b: exclusive scan -> rowptr + cursors (single block)
// ---------------------------------------------------------------------------
__global__ __launch_bounds__(1024)
void gcn_scan_kernel(int n) {
    __shared__ int warp_sums[32];
    __shared__ int s_carry;
    const int tid = threadIdx.x, lane = tid & 31, wid = tid >> 5;
    if (tid == 0) s_carry = 0;
    __syncthreads();
    for (int base = 0; base < n; base += 1024) {
        int i = base + tid;
        int v = (i < n) ? g_count[i] : 0;
        int x = v;
        #pragma unroll
        for (int d = 1; d < 32; d <<= 1) {
            int y = __shfl_up_sync(0xffffffff, x, d);
            if (lane >= d) x += y;
        }
        if (lane == 31) warp_sums[wid] = x;
        __syncthreads();
        if (wid == 0) {
            int tsum = warp_sums[lane];
            #pragma unroll
            for (int d = 1; d < 32; d <<= 1) {
                int y = __shfl_up_sync(0xffffffff, tsum, d);
                if (lane >= d) tsum += y;
            }
            warp_sums[lane] = tsum;
        }
        __syncthreads();
        int warp_off = (wid > 0) ? warp_sums[wid - 1] : 0;
        int excl = s_carry + warp_off + x - v;
        if (i < n) { g_rowptr[i] = excl; g_wofs[i] = excl; }
        __syncthreads();
        if (tid == 0) s_carry += warp_sums[31];
        __syncthreads();
    }
    if (threadIdx.x == 0) g_rowptr[n] = s_carry;
}

// ---------------------------------------------------------------------------
// Kernel 2c: scatter edges into row-sorted order
// ---------------------------------------------------------------------------
__global__ __launch_bounds__(256)
void gcn_scatter_kernel(const int* __restrict__ row,
                        const int* __restrict__ col,
                        const float* __restrict__ val, int E) {
    int e = blockIdx.x * blockDim.x + threadIdx.x;
    if (e >= E) return;
    int r = row[e];
    int p = atomicAdd(&g_wofs[r], 1);
    g_edges[p] = make_int2(col[e], __float_as_int(val[e]));
}

// ---------------------------------------------------------------------------
// Kernel 3: CSR segment reduction + fused round/bias epilogue (warp per row)
// ---------------------------------------------------------------------------
__global__ __launch_bounds__(256)
void gcn_csr_kernel(const float* __restrict__ support,
                    const float* __restrict__ bias,
                    float* __restrict__ out, int N) {
    int w    = (blockIdx.x * blockDim.x + threadIdx.x) >> 5;
    int lane = threadIdx.x & 31;
    if (w >= N) return;

    int s = g_rowptr[w];
    int e = g_rowptr[w + 1];

    float4 acc0 = make_float4(0.f, 0.f, 0.f, 0.f);
    float4 acc1 = make_float4(0.f, 0.f, 0.f, 0.f);

    int i = s;
    for (; i + 2 <= e; i += 2) {
        int2 cv0 = g_edges[i];
        int2 cv1 = g_edges[i + 1];
        float w0 = __int_as_float(cv0.y);
        float w1 = __int_as_float(cv1.y);
        const float4* s0 = (const float4*)(support + (size_t)cv0.x * F_OUT);
        const float4* s1 = (const float4*)(support + (size_t)cv1.x * F_OUT);
        float4 a0 = __ldg(s0 + lane), b0 = __ldg(s0 + lane + 32);
        float4 a1 = __ldg(s1 + lane), b1 = __ldg(s1 + lane + 32);
        acc0.x = fmaf(w0, a0.x, acc0.x);  acc0.y = fmaf(w0, a0.y, acc0.y);
        acc0.z = fmaf(w0, a0.z, acc0.z);  acc0.w = fmaf(w0, a0.w, acc0.w);
        acc1.x = fmaf(w0, b0.x, acc1.x);  acc1.y = fmaf(w0, b0.y, acc1.y);
        acc1.z = fmaf(w0, b0.z, acc1.z);  acc1.w = fmaf(w0, b0.w, acc1.w);
        acc0.x = fmaf(w1, a1.x, acc0.x);  acc0.y = fmaf(w1, a1.y, acc0.y);
        acc0.z = fmaf(w1, a1.z, acc0.z);  acc0.w = fmaf(w1, a1.w, acc0.w);
        acc1.x = fmaf(w1, b1.x, acc1.x);  acc1.y = fmaf(w1, b1.y, acc1.y);
        acc1.z = fmaf(w1, b1.z, acc1.z);  acc1.w = fmaf(w1, b1.w, acc1.w);
    }
    if (i < e) {
        int2 cv = g_edges[i];
        float w0 = __int_as_float(cv.y);
        const float4* s0 = (const float4*)(support + (size_t)cv.x * F_OUT);
        float4 a0 = __ldg(s0 + lane), b0 = __ldg(s0 + lane + 32);
        acc0.x = fmaf(w0, a0.x, acc0.x);  acc0.y = fmaf(w0, a0.y, acc0.y);
        acc0.z = fmaf(w0, a0.z, acc0.z);  acc0.w = fmaf(w0, a0.w, acc0.w);
        acc1.x = fmaf(w0, b0.x, acc1.x);  acc1.y = fmaf(w0, b0.y, acc1.y);
        acc1.z = fmaf(w0, b0.z, acc1.z);  acc1.w = fmaf(w0, b0.w, acc1.w);
    }

    float4 bi0 = __ldg((const float4*)bias + lane);
    float4 bi1 = __ldg((const float4*)bias + lane + 32);
    float4 o0, o1;
    o0.x = __fdiv_rn(rintf(acc0.x * 1000.0f), 1000.0f) + bi0.x;
    o0.y = __fdiv_rn(rintf(acc0.y * 1000.0f), 1000.0f) + bi0.y;
    o0.z = __fdiv_rn(rintf(acc0.z * 1000.0f), 1000.0f) + bi0.z;
    o0.w = __fdiv_rn(rintf(acc0.w * 1000.0f), 1000.0f) + bi0.w;
    o1.x = __fdiv_rn(rintf(acc1.x * 1000.0f), 1000.0f) + bi1.x;
    o1.y = __fdiv_rn(rintf(acc1.y * 1000.0f), 1000.0f) + bi1.y;
    o1.z = __fdiv_rn(rintf(acc1.z * 1000.0f), 1000.0f) + bi1.z;
    o1.w = __fdiv_rn(rintf(acc1.w * 1000.0f), 1000.0f) + bi1.w;

    float4* dst = (float4*)(out + (size_t)w * F_OUT);
    dst[lane]      = o0;
    dst[lane + 32] = o1;
}

// ---------------------------------------------------------------------------
// Launch
// ---------------------------------------------------------------------------
extern "C" void kernel_launch(void* const* d_in, const int* in_sizes, int n_in,
                              void* d_out, int out_size) {
    const float* x        = (const float*)d_in[0];
    const float* weight   = (const float*)d_in[1];
    const float* bias     = (const float*)d_in[2];
    const float* edge_val = (const float*)d_in[3];
    const int*   row      = (const int*)d_in[4];
    const int*   col      = (const int*)d_in[5];
    float*       out      = (float*)d_out;

    const int N = in_sizes[0] / F_IN;
    const int E = in_sizes[3];

    float* support;
    cudaGetSymbolAddress((void**)&support, g_support);
    int* count_ptr;
    cudaGetSymbolAddress((void**)&count_ptr, g_count);

    cudaMemsetAsync(count_ptr, 0, (size_t)N * sizeof(int), 0);

    const int eblocks = (E + 255) / 256;
    gcn_hist_kernel<<<eblocks, 256>>>(row, E);
    gcn_scan_kernel<<<1, 1024>>>(N);
    gcn_scatter_kernel<<<eblocks, 256>>>(row, col, edge_val, E);

    // split-bf16 tensor-core projection
    dim3 gemm_grid(F_OUT / 128, (N + 127) / 128);
    gcn_mma_gemm<<<gemm_grid, 256>>>(x, weight, support, N);

    int csr_blocks = (N * 32 + 255) / 256;
    gcn_csr_kernel<<<csr_blocks, 256>>>(support, bias, out, N);
}

// round 8
// speedup vs baseline: 2.3539x; 1.0312x over previous
#include <cuda_runtime.h>
#include <cuda_bf16.h>
#include <cstdint>

#define F_IN  512
#define F_OUT 256
#define MAX_N 100000
#define MAX_E 3200000

// ---------------- device scratch -------------------------------------------
__device__ float g_support[(size_t)MAX_N * F_OUT];          // X @ W
__device__ int   g_count[MAX_N];
__device__ int   g_rowptr[MAX_N + 1];
__device__ int   g_wofs[MAX_N];
__device__ int2  g_edges[MAX_E];

// ---------------- PTX helpers ----------------------------------------------
__device__ __forceinline__ uint32_t smem_u32(const void* p) {
    uint32_t a;
    asm("{ .reg .u64 t; cvta.to.shared.u64 t, %1; cvt.u32.u64 %0, t; }"
        : "=r"(a) : "l"(p));
    return a;
}

#define LDSM_X4(r0, r1, r2, r3, addr) \
    asm volatile("ldmatrix.sync.aligned.m8n8.x4.shared.b16 {%0,%1,%2,%3}, [%4];" \
                 : "=r"(r0), "=r"(r1), "=r"(r2), "=r"(r3) : "r"(addr))

#define LDSM_X4_T(r0, r1, r2, r3, addr) \
    asm volatile("ldmatrix.sync.aligned.m8n8.x4.trans.shared.b16 {%0,%1,%2,%3}, [%4];" \
                 : "=r"(r0), "=r"(r1), "=r"(r2), "=r"(r3) : "r"(addr))

#define MMA_BF16(d0, d1, d2, d3, a0, a1, a2, a3, b0, b1) \
    asm volatile("mma.sync.aligned.m16n8k16.row.col.f32.bf16.bf16.f32 " \
                 "{%0,%1,%2,%3}, {%4,%5,%6,%7}, {%8,%9}, {%0,%1,%2,%3};" \
                 : "+f"(d0), "+f"(d1), "+f"(d2), "+f"(d3) \
                 : "r"(a0), "r"(a1), "r"(a2), "r"(a3), "r"(b0), "r"(b1))

// split fp32x4 -> (hi bf16x4, lo bf16x4) packed as uint2 each
__device__ __forceinline__ void split4(float4 v, uint2& h, uint2& l) {
    __nv_bfloat162 h01 = __float22bfloat162_rn(make_float2(v.x, v.y));
    __nv_bfloat162 h23 = __float22bfloat162_rn(make_float2(v.z, v.w));
    float2 f01 = __bfloat1622float2(h01);
    float2 f23 = __bfloat1622float2(h23);
    __nv_bfloat162 l01 = __float22bfloat162_rn(make_float2(v.x - f01.x, v.y - f01.y));
    __nv_bfloat162 l23 = __float22bfloat162_rn(make_float2(v.z - f23.x, v.w - f23.y));
    h.x = *(uint32_t*)&h01;  h.y = *(uint32_t*)&h23;
    l.x = *(uint32_t*)&l01;  l.y = *(uint32_t*)&l23;
}

// ---------------------------------------------------------------------------
// Kernel 1: split-bf16 HMMA GEMM, double-buffered smem (1 sync per k-tile)
// CTA 128x128, 8 warps (4M x 2N), warp tile 32x64, K-tile 32.
// 3 MMAs per product: AhBh + AlBh + AhBl (fp32 accum).
// ---------------------------------------------------------------------------
#define SA_STR 40     // A smem row stride (elems)
#define SB_STR 136    // B smem row stride (elems)
#define OFF_AH 0
#define OFF_AL (128 * SA_STR * 2)                    // 10240
#define OFF_BH (OFF_AL + 128 * SA_STR * 2)           // 20480
#define OFF_BL (OFF_BH + 32 * SB_STR * 2)            // 29184
#define BUFSZ  (OFF_BL + 32 * SB_STR * 2)            // 37888
#define GEMM_SMEM (2 * BUFSZ)                        // 75776

__global__ __launch_bounds__(256, 2)
void gcn_mma_gemm(const float* __restrict__ A,   // [N, 512]
                  const float* __restrict__ W,   // [512, 256]
                  float* __restrict__ C,         // [N, 256]
                  int Nn) {
    extern __shared__ __align__(16) char dynsmem[];
    const uint32_t sb = smem_u32(dynsmem);

    const int tid   = threadIdx.x;
    const int lane  = tid & 31;
    const int wid   = tid >> 5;
    const int warpM = wid & 3;
    const int warpN = wid >> 2;
    const int m0    = blockIdx.y * 128;
    const int n0    = blockIdx.x * 128;

    float acc[2][8][4];
    #pragma unroll
    for (int i = 0; i < 2; i++)
        #pragma unroll
        for (int j = 0; j < 8; j++)
            #pragma unroll
            for (int k = 0; k < 4; k++) acc[i][j][k] = 0.0f;

    // gmem->smem mappings
    const int ar = tid >> 1;               // A row 0..127
    const int ac = (tid & 1) * 16;         // A k offset 0/16
    const int kr = tid >> 3;               // B k-row 0..31
    const int nc = (tid & 7) * 16;         // B n offset 0..112
    const int grow = m0 + ar;

    // ldmatrix per-thread address components
    const uint32_t a_row  = (uint32_t)(warpM * 32 + (lane & 15));
    const uint32_t a_colb = (uint32_t)((lane >> 4) * 8);
    const uint32_t b_k    = (uint32_t)(((lane >> 3) & 1) * 8 + (lane & 7));
    const uint32_t b_n    = (uint32_t)(warpN * 64 + (lane >> 4) * 8);

    // ---- helper lambdas ----
    auto load_A = [&](int k0, float4* av) {
        const float4* ap = (const float4*)(A + (size_t)grow * F_IN + k0 + ac);
        #pragma unroll
        for (int i = 0; i < 4; i++)
            av[i] = (grow < Nn) ? __ldg(ap + i) : make_float4(0.f, 0.f, 0.f, 0.f);
    };
    auto store_tile = [&](int nb, const float4* av, int k0) {
        char* base = dynsmem + nb * BUFSZ;
        __nv_bfloat16* pAh = (__nv_bfloat16*)(base + OFF_AH);
        __nv_bfloat16* pAl = (__nv_bfloat16*)(base + OFF_AL);
        __nv_bfloat16* pBh = (__nv_bfloat16*)(base + OFF_BH);
        __nv_bfloat16* pBl = (__nv_bfloat16*)(base + OFF_BL);
        #pragma unroll
        for (int i = 0; i < 4; i++) {
            uint2 h, l;
            split4(av[i], h, l);
            *(uint2*)(pAh + ar * SA_STR + ac + i * 4) = h;
            *(uint2*)(pAl + ar * SA_STR + ac + i * 4) = l;
        }
        const float4* bp = (const float4*)(W + (size_t)(k0 + kr) * F_OUT + n0 + nc);
        #pragma unroll
        for (int i = 0; i < 4; i++) {
            float4 v = __ldg(bp + i);
            uint2 h, l;
            split4(v, h, l);
            *(uint2*)(pBh + kr * SB_STR + nc + i * 4) = h;
            *(uint2*)(pBl + kr * SB_STR + nc + i * 4) = l;
        }
    };

    // ---- prologue: tile 0 ----
    {
        float4 av[4];
        load_A(0, av);
        store_tile(0, av, 0);
    }
    __syncthreads();

    const int NT = F_IN / 32;   // 16
    for (int t = 0; t < NT; t++) {
        const int buf = t & 1;
        const uint32_t bbase = sb + (uint32_t)(buf * BUFSZ);

        // issue next tile's A loads early (latency hides under MMAs)
        float4 av[4];
        if (t + 1 < NT) load_A((t + 1) * 32, av);

        // ---- compute from buf ----
        #pragma unroll
        for (int ks = 0; ks < 2; ks++) {
            const uint32_t aoff0 = (a_row * SA_STR + (uint32_t)(ks * 16) + a_colb) * 2;
            const uint32_t aoff1 = aoff0 + 16 * SA_STR * 2;
            const uint32_t boffk = ((b_k + (uint32_t)(ks * 16)) * SB_STR + b_n) * 2;

            uint32_t ah[8], al[8], b[16];

            LDSM_X4(ah[0], ah[1], ah[2], ah[3], bbase + OFF_AH + aoff0);
            LDSM_X4(ah[4], ah[5], ah[6], ah[7], bbase + OFF_AH + aoff1);
            #pragma unroll
            for (int lg = 0; lg < 4; lg++)
                LDSM_X4_T(b[4 * lg], b[4 * lg + 1], b[4 * lg + 2], b[4 * lg + 3],
                          bbase + OFF_BH + boffk + (uint32_t)(lg * 16) * 2);

            #pragma unroll
            for (int mf = 0; mf < 2; mf++)
                #pragma unroll
                for (int nf = 0; nf < 8; nf++)
                    MMA_BF16(acc[mf][nf][0], acc[mf][nf][1], acc[mf][nf][2], acc[mf][nf][3],
                             ah[4 * mf], ah[4 * mf + 1], ah[4 * mf + 2], ah[4 * mf + 3],
                             b[2 * nf], b[2 * nf + 1]);

            LDSM_X4(al[0], al[1], al[2], al[3], bbase + OFF_AL + aoff0);
            LDSM_X4(al[4], al[5], al[6], al[7], bbase + OFF_AL + aoff1);
            #pragma unroll
            for (int mf = 0; mf < 2; mf++)
                #pragma unroll
                for (int nf = 0; nf < 8; nf++)
                    MMA_BF16(acc[mf][nf][0], acc[mf][nf][1], acc[mf][nf][2], acc[mf][nf][3],
                             al[4 * mf], al[4 * mf + 1], al[4 * mf + 2], al[4 * mf + 3],
                             b[2 * nf], b[2 * nf + 1]);

            #pragma unroll
            for (int lg = 0; lg < 4; lg++)
                LDSM_X4_T(b[4 * lg], b[4 * lg + 1], b[4 * lg + 2], b[4 * lg + 3],
                          bbase + OFF_BL + boffk + (uint32_t)(lg * 16) * 2);
            #pragma unroll
            for (int mf = 0; mf < 2; mf++)
                #pragma unroll
                for (int nf = 0; nf < 8; nf++)
                    MMA_BF16(acc[mf][nf][0], acc[mf][nf][1], acc[mf][nf][2], acc[mf][nf][3],
                             ah[4 * mf], ah[4 * mf + 1], ah[4 * mf + 2], ah[4 * mf + 3],
                             b[2 * nf], b[2 * nf + 1]);
        }

        // ---- stage next tile into the other buffer ----
        if (t + 1 < NT) {
            store_tile(buf ^ 1, av, (t + 1) * 32);
            __syncthreads();
        }
    }

    // ---- epilogue ----
    const int g  = lane >> 2;
    const int tg = lane & 3;
    #pragma unroll
    for (int mf = 0; mf < 2; mf++) {
        #pragma unroll
        for (int nf = 0; nf < 8; nf++) {
            const int col  = n0 + warpN * 64 + nf * 8 + tg * 2;
            const int row0 = m0 + warpM * 32 + mf * 16 + g;
            const int row1 = row0 + 8;
            if (row0 < Nn)
                *(float2*)(C + (size_t)row0 * F_OUT + col) =
                    make_float2(acc[mf][nf][0], acc[mf][nf][1]);
            if (row1 < Nn)
                *(float2*)(C + (size_t)row1 * F_OUT + col) =
                    make_float2(acc[mf][nf][2], acc[mf][nf][3]);
        }
    }
}

// ---------------------------------------------------------------------------
// Kernel 2a: histogram of destination rows
// ---------------------------------------------------------------------------
__global__ __launch_bounds__(256)
void gcn_hist_kernel(const int* __restrict__ row, int E) {
    int e = blockIdx.x * blockDim.x + threadIdx.x;
    if (e < E) atomicAdd(&g_count[row[e]], 1);
}

// ---------------------------------------------------------------------------
// Kernel 2b: exclusive scan -> rowptr + cursors (single block)
// ---------------------------------------------------------------------------
__global__ __launch_bounds__(1024)
void gcn_scan_kernel(int n) {
    __shared__ int warp_sums[32];
    __shared__ int s_carry;
    const int tid = threadIdx.x, lane = tid & 31, wid = tid >> 5;
    if (tid == 0) s_carry = 0;
    __syncthreads();
    for (int base = 0; base < n; base += 1024) {
        int i = base + tid;
        int v = (i < n) ? g_count[i] : 0;
        int x = v;
        #pragma unroll
        for (int d = 1; d < 32; d <<= 1) {
            int y = __shfl_up_sync(0xffffffff, x, d);
            if (lane >= d) x += y;
        }
        if (lane == 31) warp_sums[wid] = x;
        __syncthreads();
        if (wid == 0) {
            int tsum = warp_sums[lane];
            #pragma unroll
            for (int d = 1; d < 32; d <<= 1) {
                int y = __shfl_up_sync(0xffffffff, tsum, d);
                if (lane >= d) tsum += y;
            }
            warp_sums[lane] = tsum;
        }
        __syncthreads();
        int warp_off = (wid > 0) ? warp_sums[wid - 1] : 0;
        int excl = s_carry + warp_off + x - v;
        if (i < n) { g_rowptr[i] = excl; g_wofs[i] = excl; }
        __syncthreads();
        if (tid == 0) s_carry += warp_sums[31];
        __syncthreads();
    }
    if (threadIdx.x == 0) g_rowptr[n] = s_carry;
}

// ---------------------------------------------------------------------------
// Kernel 2c: scatter edges into row-sorted order
// ---------------------------------------------------------------------------
__global__ __launch_bounds__(256)
void gcn_scatter_kernel(const int* __restrict__ row,
                        const int* __restrict__ col,
                        const float* __restrict__ val, int E) {
    int e = blockIdx.x * blockDim.x + threadIdx.x;
    if (e >= E) return;
    int r = row[e];
    int p = atomicAdd(&g_wofs[r], 1);
    g_edges[p] = make_int2(col[e], __float_as_int(val[e]));
}

// ---------------------------------------------------------------------------
// Kernel 3: CSR segment reduction + fused round/bias epilogue (warp per row)
// 4-edge unroll: 8 independent LDG.128 per lane in flight.
// ---------------------------------------------------------------------------
__device__ __forceinline__ void csr_acc(float4& acc0, float4& acc1,
                                        const float* __restrict__ support,
                                        int2 cv, int lane) {
    float wv = __int_as_float(cv.y);
    const float4* sp = (const float4*)(support + (size_t)cv.x * F_OUT);
    float4 a = __ldg(sp + lane), b = __ldg(sp + lane + 32);
    acc0.x = fmaf(wv, a.x, acc0.x);  acc0.y = fmaf(wv, a.y, acc0.y);
    acc0.z = fmaf(wv, a.z, acc0.z);  acc0.w = fmaf(wv, a.w, acc0.w);
    acc1.x = fmaf(wv, b.x, acc1.x);  acc1.y = fmaf(wv, b.y, acc1.y);
    acc1.z = fmaf(wv, b.z, acc1.z);  acc1.w = fmaf(wv, b.w, acc1.w);
}

__global__ __launch_bounds__(256)
void gcn_csr_kernel(const float* __restrict__ support,
                    const float* __restrict__ bias,
                    float* __restrict__ out, int N) {
    int w    = (blockIdx.x * blockDim.x + threadIdx.x) >> 5;
    int lane = threadIdx.x & 31;
    if (w >= N) return;

    int s = g_rowptr[w];
    int e = g_rowptr[w + 1];

    float4 acc0 = make_float4(0.f, 0.f, 0.f, 0.f);
    float4 acc1 = make_float4(0.f, 0.f, 0.f, 0.f);

    int i = s;
    for (; i + 4 <= e; i += 4) {
        int2 cv0 = g_edges[i];
        int2 cv1 = g_edges[i + 1];
        int2 cv2 = g_edges[i + 2];
        int2 cv3 = g_edges[i + 3];
        float w0 = __int_as_float(cv0.y), w1 = __int_as_float(cv1.y);
        float w2 = __int_as_float(cv2.y), w3 = __int_as_float(cv3.y);
        const float4* s0 = (const float4*)(support + (size_t)cv0.x * F_OUT);
        const float4* s1 = (const float4*)(support + (size_t)cv1.x * F_OUT);
        const float4* s2 = (const float4*)(support + (size_t)cv2.x * F_OUT);
        const float4* s3 = (const float4*)(support + (size_t)cv3.x * F_OUT);
        float4 a0 = __ldg(s0 + lane), b0 = __ldg(s0 + lane + 32);
        float4 a1 = __ldg(s1 + lane), b1 = __ldg(s1 + lane + 32);
        float4 a2 = __ldg(s2 + lane), b2 = __ldg(s2 + lane + 32);
        float4 a3 = __ldg(s3 + lane), b3 = __ldg(s3 + lane + 32);
        acc0.x = fmaf(w0, a0.x, acc0.x);  acc0.y = fmaf(w0, a0.y, acc0.y);
        acc0.z = fmaf(w0, a0.z, acc0.z);  acc0.w = fmaf(w0, a0.w, acc0.w);
        acc1.x = fmaf(w0, b0.x, acc1.x);  acc1.y = fmaf(w0, b0.y, acc1.y);
        acc1.z = fmaf(w0, b0.z, acc1.z);  acc1.w = fmaf(w0, b0.w, acc1.w);
        acc0.x = fmaf(w1, a1.x, acc0.x);  acc0.y = fmaf(w1, a1.y, acc0.y);
        acc0.z = fmaf(w1, a1.z, acc0.z);  acc0.w = fmaf(w1, a1.w, acc0.w);
        acc1.x = fmaf(w1, b1.x, acc1.x);  acc1.y = fmaf(w1, b1.y, acc1.y);
        acc1.z = fmaf(w1, b1.z, acc1.z);  acc1.w = fmaf(w1, b1.w, acc1.w);
        acc0.x = fmaf(w2, a2.x, acc0.x);  acc0.y = fmaf(w2, a2.y, acc0.y);
        acc0.z = fmaf(w2, a2.z, acc0.z);  acc0.w = fmaf(w2, a2.w, acc0.w);
        acc1.x = fmaf(w2, b2.x, acc1.x);  acc1.y = fmaf(w2, b2.y, acc1.y);
        acc1.z = fmaf(w2, b2.z, acc1.z);  acc1.w = fmaf(w2, b2.w, acc1.w);
        acc0.x = fmaf(w3, a3.x, acc0.x);  acc0.y = fmaf(w3, a3.y, acc0.y);
        acc0.z = fmaf(w3, a3.z, acc0.z);  acc0.w = fmaf(w3, a3.w, acc0.w);
        acc1.x = fmaf(w3, b3.x, acc1.x);  acc1.y = fmaf(w3, b3.y, acc1.y);
        acc1.z = fmaf(w3, b3.z, acc1.z);  acc1.w = fmaf(w3, b3.w, acc1.w);
    }
    for (; i < e; i++)
        csr_acc(acc0, acc1, support, g_edges[i], lane);

    float4 bi0 = __ldg((const float4*)bias + lane);
    float4 bi1 = __ldg((const float4*)bias + lane + 32);
    float4 o0, o1;
    o0.x = __fdiv_rn(rintf(acc0.x * 1000.0f), 1000.0f) + bi0.x;
    o0.y = __fdiv_rn(rintf(acc0.y * 1000.0f), 1000.0f) + bi0.y;
    o0.z = __fdiv_rn(rintf(acc0.z * 1000.0f), 1000.0f) + bi0.z;
    o0.w = __fdiv_rn(rintf(acc0.w * 1000.0f), 1000.0f) + bi0.w;
    o1.x = __fdiv_rn(rintf(acc1.x * 1000.0f), 1000.0f) + bi1.x;
    o1.y = __fdiv_rn(rintf(acc1.y * 1000.0f), 1000.0f) + bi1.y;
    o1.z = __fdiv_rn(rintf(acc1.z * 1000.0f), 1000.0f) + bi1.z;
    o1.w = __fdiv_rn(rintf(acc1.w * 1000.0f), 1000.0f) + bi1.w;

    float4* dst = (float4*)(out + (size_t)w * F_OUT);
    dst[lane]      = o0;
    dst[lane + 32] = o1;
}

// ---------------------------------------------------------------------------
// Launch — CSR build chain forked onto a side stream to overlap with GEMM.
// Streams/events created on the first (un-captured correctness) call.
// ---------------------------------------------------------------------------
extern "C" void kernel_launch(void* const* d_in, const int* in_sizes, int n_in,
                              void* d_out, int out_size) {
    const float* x        = (const float*)d_in[0];
    const float* weight   = (const float*)d_in[1];
    const float* bias     = (const float*)d_in[2];
    const float* edge_val = (const float*)d_in[3];
    const int*   row      = (const int*)d_in[4];
    const int*   col      = (const int*)d_in[5];
    float*       out      = (float*)d_out;

    const int N = in_sizes[0] / F_IN;
    const int E = in_sizes[3];

    float* support;
    cudaGetSymbolAddress((void**)&support, g_support);
    int* count_ptr;
    cudaGetSymbolAddress((void**)&count_ptr, g_count);

    static cudaStream_t s1 = nullptr;
    static cudaEvent_t ev_fork = nullptr, ev_join = nullptr;
    static bool init_done = false;
    if (!init_done) {
        cudaStreamCreateWithFlags(&s1, cudaStreamNonBlocking);
        cudaEventCreateWithFlags(&ev_fork, cudaEventDisableTiming);
        cudaEventCreateWithFlags(&ev_join, cudaEventDisableTiming);
        cudaFuncSetAttribute(gcn_mma_gemm,
                             cudaFuncAttributeMaxDynamicSharedMemorySize, GEMM_SMEM);
        init_done = true;
    }

    const int eblocks = (E + 255) / 256;

    // fork: CSR build chain on s1, GEMM on main stream
    cudaEventRecord(ev_fork, 0);
    cudaStreamWaitEvent(s1, ev_fork, 0);

    cudaMemsetAsync(count_ptr, 0, (size_t)N * sizeof(int), s1);
    gcn_hist_kernel<<<eblocks, 256, 0, s1>>>(row, E);
    gcn_scan_kernel<<<1, 1024, 0, s1>>>(N);
    gcn_scatter_kernel<<<eblocks, 256, 0, s1>>>(row, col, edge_val, E);
    cudaEventRecord(ev_join, s1);

    dim3 gemm_grid(F_OUT / 128, (N + 127) / 128);
    gcn_mma_gemm<<<gemm_grid, 256, GEMM_SMEM>>>(x, weight, support, N);

    // join: CSR reduce needs both support and sorted edges
    cudaStreamWaitEvent(0, ev_join, 0);
    int csr_blocks = (N * 32 + 255) / 256;
    gcn_csr_kernel<<<csr_blocks, 256>>>(support, bias, out, N);
}

// round 9
// speedup vs baseline: 2.7423x; 1.1650x over previous
#include <cuda_runtime.h>
#include <cuda_bf16.h>
#include <cuda_fp16.h>
#include <cstdint>

#define F_IN  512
#define F_OUT 256
#define MAX_N 100000
#define MAX_E 3200000

// ---------------- device scratch -------------------------------------------
__device__ __half g_supportH[(size_t)MAX_N * F_OUT];        // X @ W  (fp16, 51 MB: L2-resident)
__device__ int    g_count[MAX_N];
__device__ int    g_rowptr[MAX_N + 1];
__device__ int    g_wofs[MAX_N];
__device__ int2   g_edges[MAX_E];

// ---------------- PTX helpers ----------------------------------------------
__device__ __forceinline__ uint32_t smem_u32(const void* p) {
    uint32_t a;
    asm("{ .reg .u64 t; cvta.to.shared.u64 t, %1; cvt.u32.u64 %0, t; }"
        : "=r"(a) : "l"(p));
    return a;
}

#define LDSM_X4(r0, r1, r2, r3, addr) \
    asm volatile("ldmatrix.sync.aligned.m8n8.x4.shared.b16 {%0,%1,%2,%3}, [%4];" \
                 : "=r"(r0), "=r"(r1), "=r"(r2), "=r"(r3) : "r"(addr))

#define LDSM_X4_T(r0, r1, r2, r3, addr) \
    asm volatile("ldmatrix.sync.aligned.m8n8.x4.trans.shared.b16 {%0,%1,%2,%3}, [%4];" \
                 : "=r"(r0), "=r"(r1), "=r"(r2), "=r"(r3) : "r"(addr))

#define MMA_BF16(d0, d1, d2, d3, a0, a1, a2, a3, b0, b1) \
    asm volatile("mma.sync.aligned.m16n8k16.row.col.f32.bf16.bf16.f32 " \
                 "{%0,%1,%2,%3}, {%4,%5,%6,%7}, {%8,%9}, {%0,%1,%2,%3};" \
                 : "+f"(d0), "+f"(d1), "+f"(d2), "+f"(d3) \
                 : "r"(a0), "r"(a1), "r"(a2), "r"(a3), "r"(b0), "r"(b1))

// split fp32x4 -> (hi bf16x4, lo bf16x4) packed as uint2 each
__device__ __forceinline__ void split4(float4 v, uint2& h, uint2& l) {
    __nv_bfloat162 h01 = __float22bfloat162_rn(make_float2(v.x, v.y));
    __nv_bfloat162 h23 = __float22bfloat162_rn(make_float2(v.z, v.w));
    float2 f01 = __bfloat1622float2(h01);
    float2 f23 = __bfloat1622float2(h23);
    __nv_bfloat162 l01 = __float22bfloat162_rn(make_float2(v.x - f01.x, v.y - f01.y));
    __nv_bfloat162 l23 = __float22bfloat162_rn(make_float2(v.z - f23.x, v.w - f23.y));
    h.x = *(uint32_t*)&h01;  h.y = *(uint32_t*)&h23;
    l.x = *(uint32_t*)&l01;  l.y = *(uint32_t*)&l23;
}

// ---------------------------------------------------------------------------
// Kernel 1: split-bf16 HMMA GEMM (R6 single-buffer structure — HMMA-roofline
// bound at ~512 MACs/cyc/SM, scheduling changes proven neutral).
// Output stored as fp16.
// ---------------------------------------------------------------------------
#define SA_STR 40
#define SB_STR 136

__global__ __launch_bounds__(256, 2)
void gcn_mma_gemm(const float* __restrict__ A,   // [N, 512]
                  const float* __restrict__ W,   // [512, 256]
                  __half* __restrict__ C,        // [N, 256] fp16
                  int Nn) {
    __shared__ __align__(16) __nv_bfloat16 sAh[128 * SA_STR];
    __shared__ __align__(16) __nv_bfloat16 sAl[128 * SA_STR];
    __shared__ __align__(16) __nv_bfloat16 sBh[32 * SB_STR];
    __shared__ __align__(16) __nv_bfloat16 sBl[32 * SB_STR];

    const int tid   = threadIdx.x;
    const int lane  = tid & 31;
    const int wid   = tid >> 5;
    const int warpM = wid & 3;
    const int warpN = wid >> 2;
    const int m0    = blockIdx.y * 128;
    const int n0    = blockIdx.x * 128;

    const uint32_t sAh_b = smem_u32(sAh);
    const uint32_t sAl_b = smem_u32(sAl);
    const uint32_t sBh_b = smem_u32(sBh);
    const uint32_t sBl_b = smem_u32(sBl);

    float acc[2][8][4];
    #pragma unroll
    for (int i = 0; i < 2; i++)
        #pragma unroll
        for (int j = 0; j < 8; j++)
            #pragma unroll
            for (int k = 0; k < 4; k++) acc[i][j][k] = 0.0f;

    const int ar = tid >> 1;
    const int ac = (tid & 1) * 16;
    const int kr = tid >> 3;
    const int nc = (tid & 7) * 16;

    const uint32_t a_row  = (uint32_t)(warpM * 32 + (lane & 15));
    const uint32_t a_colb = (uint32_t)((lane >> 4) * 8);
    const uint32_t b_k    = (uint32_t)(((lane >> 3) & 1) * 8 + (lane & 7));
    const uint32_t b_n    = (uint32_t)(warpN * 64 + (lane >> 4) * 8);

    for (int kt = 0; kt < F_IN / 32; kt++) {
        const int k0 = kt * 32;
        {
            const int grow = m0 + ar;
            const float4* ap = (const float4*)(A + (size_t)grow * F_IN + k0 + ac);
            #pragma unroll
            for (int i = 0; i < 4; i++) {
                float4 v = (grow < Nn) ? __ldg(ap + i)
                                       : make_float4(0.f, 0.f, 0.f, 0.f);
                uint2 h, l;
                split4(v, h, l);
                *(uint2*)(sAh + ar * SA_STR + ac + i * 4) = h;
                *(uint2*)(sAl + ar * SA_STR + ac + i * 4) = l;
            }
            const float4* bp = (const float4*)(W + (size_t)(k0 + kr) * F_OUT + n0 + nc);
            #pragma unroll
            for (int i = 0; i < 4; i++) {
                float4 v = __ldg(bp + i);
                uint2 h, l;
                split4(v, h, l);
                *(uint2*)(sBh + kr * SB_STR + nc + i * 4) = h;
                *(uint2*)(sBl + kr * SB_STR + nc + i * 4) = l;
            }
        }
        __syncthreads();

        #pragma unroll
        for (int ks = 0; ks < 2; ks++) {
            const uint32_t aoff0 = (a_row * SA_STR + (uint32_t)(ks * 16) + a_colb) * 2;
            const uint32_t aoff1 = aoff0 + 16 * SA_STR * 2;
            const uint32_t boffk = ((b_k + (uint32_t)(ks * 16)) * SB_STR + b_n) * 2;

            uint32_t ah[8], al[8], b[16];

            LDSM_X4(ah[0], ah[1], ah[2], ah[3], sAh_b + aoff0);
            LDSM_X4(ah[4], ah[5], ah[6], ah[7], sAh_b + aoff1);
            #pragma unroll
            for (int lg = 0; lg < 4; lg++)
                LDSM_X4_T(b[4 * lg], b[4 * lg + 1], b[4 * lg + 2], b[4 * lg + 3],
                          sBh_b + boffk + (uint32_t)(lg * 16) * 2);

            #pragma unroll
            for (int mf = 0; mf < 2; mf++)
                #pragma unroll
                for (int nf = 0; nf < 8; nf++)
                    MMA_BF16(acc[mf][nf][0], acc[mf][nf][1], acc[mf][nf][2], acc[mf][nf][3],
                             ah[4 * mf], ah[4 * mf + 1], ah[4 * mf + 2], ah[4 * mf + 3],
                             b[2 * nf], b[2 * nf + 1]);

            LDSM_X4(al[0], al[1], al[2], al[3], sAl_b + aoff0);
            LDSM_X4(al[4], al[5], al[6], al[7], sAl_b + aoff1);
            #pragma unroll
            for (int mf = 0; mf < 2; mf++)
                #pragma unroll
                for (int nf = 0; nf < 8; nf++)
                    MMA_BF16(acc[mf][nf][0], acc[mf][nf][1], acc[mf][nf][2], acc[mf][nf][3],
                             al[4 * mf], al[4 * mf + 1], al[4 * mf + 2], al[4 * mf + 3],
                             b[2 * nf], b[2 * nf + 1]);

            #pragma unroll
            for (int lg = 0; lg < 4; lg++)
                LDSM_X4_T(b[4 * lg], b[4 * lg + 1], b[4 * lg + 2], b[4 * lg + 3],
                          sBl_b + boffk + (uint32_t)(lg * 16) * 2);
            #pragma unroll
            for (int mf = 0; mf < 2; mf++)
                #pragma unroll
                for (int nf = 0; nf < 8; nf++)
                    MMA_BF16(acc[mf][nf][0], acc[mf][nf][1], acc[mf][nf][2], acc[mf][nf][3],
                             ah[4 * mf], ah[4 * mf + 1], ah[4 * mf + 2], ah[4 * mf + 3],
                             b[2 * nf], b[2 * nf + 1]);
        }
        __syncthreads();
    }

    // ---- epilogue: fp16 stores ----
    const int g  = lane >> 2;
    const int tg = lane & 3;
    #pragma unroll
    for (int mf = 0; mf < 2; mf++) {
        #pragma unroll
        for (int nf = 0; nf < 8; nf++) {
            const int col  = n0 + warpN * 64 + nf * 8 + tg * 2;
            const int row0 = m0 + warpM * 32 + mf * 16 + g;
            const int row1 = row0 + 8;
            if (row0 < Nn)
                *(__half2*)(C + (size_t)row0 * F_OUT + col) =
                    __floats2half2_rn(acc[mf][nf][0], acc[mf][nf][1]);
            if (row1 < Nn)
                *(__half2*)(C + (size_t)row1 * F_OUT + col) =
                    __floats2half2_rn(acc[mf][nf][2], acc[mf][nf][3]);
        }
    }
}

// ---------------------------------------------------------------------------
// Kernel 2a: histogram of destination rows
// ---------------------------------------------------------------------------
__global__ __launch_bounds__(256)
void gcn_hist_kernel(const int* __restrict__ row, int E) {
    int e = blockIdx.x * blockDim.x + threadIdx.x;
    if (e < E) atomicAdd(&g_count[row[e]], 1);
}

// ---------------------------------------------------------------------------
// Kernel 2b: exclusive scan -> rowptr + cursors (single block)
// ---------------------------------------------------------------------------
__global__ __launch_bounds__(1024)
void gcn_scan_kernel(int n) {
    __shared__ int warp_sums[32];
    __shared__ int s_carry;
    const int tid = threadIdx.x, lane = tid & 31, wid = tid >> 5;
    if (tid == 0) s_carry = 0;
    __syncthreads();
    for (int base = 0; base < n; base += 1024) {
        int i = base + tid;
        int v = (i < n) ? g_count[i] : 0;
        int x = v;
        #pragma unroll
        for (int d = 1; d < 32; d <<= 1) {
            int y = __shfl_up_sync(0xffffffff, x, d);
            if (lane >= d) x += y;
        }
        if (lane == 31) warp_sums[wid] = x;
        __syncthreads();
        if (wid == 0) {
            int tsum = warp_sums[lane];
            #pragma unroll
            for (int d = 1; d < 32; d <<= 1) {
                int y = __shfl_up_sync(0xffffffff, tsum, d);
                if (lane >= d) tsum += y;
            }
            warp_sums[lane] = tsum;
        }
        __syncthreads();
        int warp_off = (wid > 0) ? warp_sums[wid - 1] : 0;
        int excl = s_carry + warp_off + x - v;
        if (i < n) { g_rowptr[i] = excl; g_wofs[i] = excl; }
        __syncthreads();
        if (tid == 0) s_carry += warp_sums[31];
        __syncthreads();
    }
    if (threadIdx.x == 0) g_rowptr[n] = s_carry;
}

// ---------------------------------------------------------------------------
// Kernel 2c: scatter edges into row-sorted order
// ---------------------------------------------------------------------------
__global__ __launch_bounds__(256)
void gcn_scatter_kernel(const int* __restrict__ row,
                        const int* __restrict__ col,
                        const float* __restrict__ val, int E) {
    int e = blockIdx.x * blockDim.x + threadIdx.x;
    if (e >= E) return;
    int r = row[e];
    int p = atomicAdd(&g_wofs[r], 1);
    g_edges[p] = make_int2(col[e], __float_as_int(val[e]));
}

// ---------------------------------------------------------------------------
// Kernel 3: CSR segment reduction over fp16 support (warp per row)
// Lane covers 8 cols (one uint4 = 8 halves per edge). 4-edge unroll for MLP.
// ---------------------------------------------------------------------------
__device__ __forceinline__ void acc_edge(float acc[8], uint4 v, float wv) {
    const __half2* h = (const __half2*)&v;
    #pragma unroll
    for (int p = 0; p < 4; p++) {
        float2 f = __half22float2(h[p]);
        acc[2 * p + 0] = fmaf(wv, f.x, acc[2 * p + 0]);
        acc[2 * p + 1] = fmaf(wv, f.y, acc[2 * p + 1]);
    }
}

__global__ __launch_bounds__(256)
void gcn_csr_kernel(const __half* __restrict__ support,
                    const float* __restrict__ bias,
                    float* __restrict__ out, int N) {
    int w    = (blockIdx.x * blockDim.x + threadIdx.x) >> 5;
    int lane = threadIdx.x & 31;
    if (w >= N) return;

    int s = g_rowptr[w];
    int e = g_rowptr[w + 1];

    float acc[8];
    #pragma unroll
    for (int j = 0; j < 8; j++) acc[j] = 0.0f;

    int i = s;
    for (; i + 4 <= e; i += 4) {
        int2 cv0 = g_edges[i];
        int2 cv1 = g_edges[i + 1];
        int2 cv2 = g_edges[i + 2];
        int2 cv3 = g_edges[i + 3];
        uint4 v0 = __ldg((const uint4*)(support + (size_t)cv0.x * F_OUT) + lane);
        uint4 v1 = __ldg((const uint4*)(support + (size_t)cv1.x * F_OUT) + lane);
        uint4 v2 = __ldg((const uint4*)(support + (size_t)cv2.x * F_OUT) + lane);
        uint4 v3 = __ldg((const uint4*)(support + (size_t)cv3.x * F_OUT) + lane);
        acc_edge(acc, v0, __int_as_float(cv0.y));
        acc_edge(acc, v1, __int_as_float(cv1.y));
        acc_edge(acc, v2, __int_as_float(cv2.y));
        acc_edge(acc, v3, __int_as_float(cv3.y));
    }
    for (; i < e; i++) {
        int2 cv = g_edges[i];
        uint4 v = __ldg((const uint4*)(support + (size_t)cv.x * F_OUT) + lane);
        acc_edge(acc, v, __int_as_float(cv.y));
    }

    // fused epilogue: round-half-even(x*1000)/1000 + bias; cols lane*8..lane*8+7
    float4 bi0 = __ldg((const float4*)bias + lane * 2);
    float4 bi1 = __ldg((const float4*)bias + lane * 2 + 1);
    float4 o0, o1;
    o0.x = __fdiv_rn(rintf(acc[0] * 1000.0f), 1000.0f) + bi0.x;
    o0.y = __fdiv_rn(rintf(acc[1] * 1000.0f), 1000.0f) + bi0.y;
    o0.z = __fdiv_rn(rintf(acc[2] * 1000.0f), 1000.0f) + bi0.z;
    o0.w = __fdiv_rn(rintf(acc[3] * 1000.0f), 1000.0f) + bi0.w;
    o1.x = __fdiv_rn(rintf(acc[4] * 1000.0f), 1000.0f) + bi1.x;
    o1.y = __fdiv_rn(rintf(acc[5] * 1000.0f), 1000.0f) + bi1.y;
    o1.z = __fdiv_rn(rintf(acc[6] * 1000.0f), 1000.0f) + bi1.z;
    o1.w = __fdiv_rn(rintf(acc[7] * 1000.0f), 1000.0f) + bi1.w;

    float4* dst = (float4*)(out + (size_t)w * F_OUT + lane * 8);
    dst[0] = o0;
    dst[1] = o1;
}

// ---------------------------------------------------------------------------
// Launch — CSR build chain on a side stream (overlaps the GEMM).
// ---------------------------------------------------------------------------
extern "C" void kernel_launch(void* const* d_in, const int* in_sizes, int n_in,
                              void* d_out, int out_size) {
    const float* x        = (const float*)d_in[0];
    const float* weight   = (const float*)d_in[1];
    const float* bias     = (const float*)d_in[2];
    const float* edge_val = (const float*)d_in[3];
    const int*   row      = (const int*)d_in[4];
    const int*   col      = (const int*)d_in[5];
    float*       out      = (float*)d_out;

    const int N = in_sizes[0] / F_IN;
    const int E = in_sizes[3];

    __half* support;
    cudaGetSymbolAddress((void**)&support, g_supportH);
    int* count_ptr;
    cudaGetSymbolAddress((void**)&count_ptr, g_count);

    static cudaStream_t s1 = nullptr;
    static cudaEvent_t ev_fork = nullptr, ev_join = nullptr;
    static bool init_done = false;
    if (!init_done) {
        cudaStreamCreateWithFlags(&s1, cudaStreamNonBlocking);
        cudaEventCreateWithFlags(&ev_fork, cudaEventDisableTiming);
        cudaEventCreateWithFlags(&ev_join, cudaEventDisableTiming);
        init_done = true;
    }

    const int eblocks = (E + 255) / 256;

    // fork: CSR build chain on s1, GEMM on main stream
    cudaEventRecord(ev_fork, 0);
    cudaStreamWaitEvent(s1, ev_fork, 0);

    cudaMemsetAsync(count_ptr, 0, (size_t)N * sizeof(int), s1);
    gcn_hist_kernel<<<eblocks, 256, 0, s1>>>(row, E);
    gcn_scan_kernel<<<1, 1024, 0, s1>>>(N);
    gcn_scatter_kernel<<<eblocks, 256, 0, s1>>>(row, col, edge_val, E);
    cudaEventRecord(ev_join, s1);

    dim3 gemm_grid(F_OUT / 128, (N + 127) / 128);
    gcn_mma_gemm<<<gemm_grid, 256>>>(x, weight, support, N);

    // join: CSR reduce needs both support and sorted edges
    cudaStreamWaitEvent(0, ev_join, 0);
    int csr_blocks = (N * 32 + 255) / 256;
    gcn_csr_kernel<<<csr_blocks, 256>>>(support, bias, out, N);
}

// round 10
// speedup vs baseline: 3.1114x; 1.1346x over previous
#include <cuda_runtime.h>
#include <cuda_fp16.h>
#include <cstdint>

#define F_IN  512
#define F_OUT 256
#define MAX_N 100000
#define MAX_E 3200000

// ---------------- device scratch -------------------------------------------
__device__ __half g_supportH[(size_t)MAX_N * F_OUT];        // X @ W  (fp16, 51 MB: L2-resident)
__device__ int    g_count[MAX_N];
__device__ int    g_rowptr[MAX_N + 1];
__device__ int    g_wofs[MAX_N];
__device__ int2   g_edges[MAX_E];

// ---------------- PTX helpers ----------------------------------------------
__device__ __forceinline__ uint32_t smem_u32(const void* p) {
    uint32_t a;
    asm("{ .reg .u64 t; cvta.to.shared.u64 t, %1; cvt.u32.u64 %0, t; }"
        : "=r"(a) : "l"(p));
    return a;
}

#define LDSM_X4(r0, r1, r2, r3, addr) \
    asm volatile("ldmatrix.sync.aligned.m8n8.x4.shared.b16 {%0,%1,%2,%3}, [%4];" \
                 : "=r"(r0), "=r"(r1), "=r"(r2), "=r"(r3) : "r"(addr))

#define LDSM_X4_T(r0, r1, r2, r3, addr) \
    asm volatile("ldmatrix.sync.aligned.m8n8.x4.trans.shared.b16 {%0,%1,%2,%3}, [%4];" \
                 : "=r"(r0), "=r"(r1), "=r"(r2), "=r"(r3) : "r"(addr))

#define MMA_F16(d0, d1, d2, d3, a0, a1, a2, a3, b0, b1) \
    asm volatile("mma.sync.aligned.m16n8k16.row.col.f32.f16.f16.f32 " \
                 "{%0,%1,%2,%3}, {%4,%5,%6,%7}, {%8,%9}, {%0,%1,%2,%3};" \
                 : "+f"(d0), "+f"(d1), "+f"(d2), "+f"(d3) \
                 : "r"(a0), "r"(a1), "r"(a2), "r"(a3), "r"(b0), "r"(b1))

// split fp32x4 -> (hi f16x4, lo f16x4) packed as uint2 each
__device__ __forceinline__ void split4h(float4 v, uint2& h, uint2& l) {
    __half2 h01 = __floats2half2_rn(v.x, v.y);
    __half2 h23 = __floats2half2_rn(v.z, v.w);
    float2 f01 = __half22float2(h01);
    float2 f23 = __half22float2(h23);
    __half2 l01 = __floats2half2_rn(v.x - f01.x, v.y - f01.y);
    __half2 l23 = __floats2half2_rn(v.z - f23.x, v.w - f23.y);
    h.x = *(uint32_t*)&h01;  h.y = *(uint32_t*)&h23;
    l.x = *(uint32_t*)&l01;  l.y = *(uint32_t*)&l23;
}
// fp32x4 -> f16x4 packed as uint2
__device__ __forceinline__ uint2 pack4h(float4 v) {
    __half2 p01 = __floats2half2_rn(v.x, v.y);
    __half2 p23 = __floats2half2_rn(v.z, v.w);
    uint2 r;
    r.x = *(uint32_t*)&p01;  r.y = *(uint32_t*)&p23;
    return r;
}

// ---------------------------------------------------------------------------
// Kernel 1: 2-term split-fp16 HMMA GEMM  support = X @ W
// A split hi/lo fp16 (22-bit effective), B single fp16 (2^-11 trunc).
// C = Ah*B + Al*B : 64 MMAs per k-tile (vs 96 for the 3-term bf16 variant).
// CTA 128x128, 8 warps (4M x 2N), K-tile 32. Output fp16.
// ---------------------------------------------------------------------------
#define SA_STR 40
#define SB_STR 136

__global__ __launch_bounds__(256, 2)
void gcn_mma_gemm(const float* __restrict__ A,   // [N, 512]
                  const float* __restrict__ W,   // [512, 256]
                  __half* __restrict__ C,        // [N, 256] fp16
                  int Nn) {
    __shared__ __align__(16) __half sAh[128 * SA_STR];
    __shared__ __align__(16) __half sAl[128 * SA_STR];
    __shared__ __align__(16) __half sB [32 * SB_STR];

    const int tid   = threadIdx.x;
    const int lane  = tid & 31;
    const int wid   = tid >> 5;
    const int warpM = wid & 3;
    const int warpN = wid >> 2;
    const int m0    = blockIdx.y * 128;
    const int n0    = blockIdx.x * 128;

    const uint32_t sAh_b = smem_u32(sAh);
    const uint32_t sAl_b = smem_u32(sAl);
    const uint32_t sB_b  = smem_u32(sB);

    float acc[2][8][4];
    #pragma unroll
    for (int i = 0; i < 2; i++)
        #pragma unroll
        for (int j = 0; j < 8; j++)
            #pragma unroll
            for (int k = 0; k < 4; k++) acc[i][j][k] = 0.0f;

    const int ar = tid >> 1;
    const int ac = (tid & 1) * 16;
    const int kr = tid >> 3;
    const int nc = (tid & 7) * 16;

    const uint32_t a_row  = (uint32_t)(warpM * 32 + (lane & 15));
    const uint32_t a_colb = (uint32_t)((lane >> 4) * 8);
    const uint32_t b_k    = (uint32_t)(((lane >> 3) & 1) * 8 + (lane & 7));
    const uint32_t b_n    = (uint32_t)(warpN * 64 + (lane >> 4) * 8);

    for (int kt = 0; kt < F_IN / 32; kt++) {
        const int k0 = kt * 32;
        {
            const int grow = m0 + ar;
            const float4* ap = (const float4*)(A + (size_t)grow * F_IN + k0 + ac);
            #pragma unroll
            for (int i = 0; i < 4; i++) {
                float4 v = (grow < Nn) ? __ldg(ap + i)
                                       : make_float4(0.f, 0.f, 0.f, 0.f);
                uint2 h, l;
                split4h(v, h, l);
                *(uint2*)(sAh + ar * SA_STR + ac + i * 4) = h;
                *(uint2*)(sAl + ar * SA_STR + ac + i * 4) = l;
            }
            const float4* bp = (const float4*)(W + (size_t)(k0 + kr) * F_OUT + n0 + nc);
            #pragma unroll
            for (int i = 0; i < 4; i++)
                *(uint2*)(sB + kr * SB_STR + nc + i * 4) = pack4h(__ldg(bp + i));
        }
        __syncthreads();

        #pragma unroll
        for (int ks = 0; ks < 2; ks++) {
            const uint32_t aoff0 = (a_row * SA_STR + (uint32_t)(ks * 16) + a_colb) * 2;
            const uint32_t aoff1 = aoff0 + 16 * SA_STR * 2;
            const uint32_t boffk = ((b_k + (uint32_t)(ks * 16)) * SB_STR + b_n) * 2;

            uint32_t ah[8], al[8], b[16];

            LDSM_X4(ah[0], ah[1], ah[2], ah[3], sAh_b + aoff0);
            LDSM_X4(ah[4], ah[5], ah[6], ah[7], sAh_b + aoff1);
            #pragma unroll
            for (int lg = 0; lg < 4; lg++)
                LDSM_X4_T(b[4 * lg], b[4 * lg + 1], b[4 * lg + 2], b[4 * lg + 3],
                          sB_b + boffk + (uint32_t)(lg * 16) * 2);

            #pragma unroll
            for (int mf = 0; mf < 2; mf++)
                #pragma unroll
                for (int nf = 0; nf < 8; nf++)
                    MMA_F16(acc[mf][nf][0], acc[mf][nf][1], acc[mf][nf][2], acc[mf][nf][3],
                            ah[4 * mf], ah[4 * mf + 1], ah[4 * mf + 2], ah[4 * mf + 3],
                            b[2 * nf], b[2 * nf + 1]);

            LDSM_X4(al[0], al[1], al[2], al[3], sAl_b + aoff0);
            LDSM_X4(al[4], al[5], al[6], al[7], sAl_b + aoff1);
            #pragma unroll
            for (int mf = 0; mf < 2; mf++)
                #pragma unroll
                for (int nf = 0; nf < 8; nf++)
                    MMA_F16(acc[mf][nf][0], acc[mf][nf][1], acc[mf][nf][2], acc[mf][nf][3],
                            al[4 * mf], al[4 * mf + 1], al[4 * mf + 2], al[4 * mf + 3],
                            b[2 * nf], b[2 * nf + 1]);
        }
        __syncthreads();
    }

    // ---- epilogue: fp16 stores ----
    const int g  = lane >> 2;
    const int tg = lane & 3;
    #pragma unroll
    for (int mf = 0; mf < 2; mf++) {
        #pragma unroll
        for (int nf = 0; nf < 8; nf++) {
            const int col  = n0 + warpN * 64 + nf * 8 + tg * 2;
            const int row0 = m0 + warpM * 32 + mf * 16 + g;
            const int row1 = row0 + 8;
            if (row0 < Nn)
                *(__half2*)(C + (size_t)row0 * F_OUT + col) =
                    __floats2half2_rn(acc[mf][nf][0], acc[mf][nf][1]);
            if (row1 < Nn)
                *(__half2*)(C + (size_t)row1 * F_OUT + col) =
                    __floats2half2_rn(acc[mf][nf][2], acc[mf][nf][3]);
        }
    }
}

// ---------------------------------------------------------------------------
// Kernel 2a: histogram of destination rows
// ---------------------------------------------------------------------------
__global__ __launch_bounds__(256)
void gcn_hist_kernel(const int* __restrict__ row, int E) {
    int e = blockIdx.x * blockDim.x + threadIdx.x;
    if (e < E) atomicAdd(&g_count[row[e]], 1);
}

// ---------------------------------------------------------------------------
// Kernel 2b: exclusive scan -> rowptr + cursors (single block)
// ---------------------------------------------------------------------------
__global__ __launch_bounds__(1024)
void gcn_scan_kernel(int n) {
    __shared__ int warp_sums[32];
    __shared__ int s_carry;
    const int tid = threadIdx.x, lane = tid & 31, wid = tid >> 5;
    if (tid == 0) s_carry = 0;
    __syncthreads();
    for (int base = 0; base < n; base += 1024) {
        int i = base + tid;
        int v = (i < n) ? g_count[i] : 0;
        int x = v;
        #pragma unroll
        for (int d = 1; d < 32; d <<= 1) {
            int y = __shfl_up_sync(0xffffffff, x, d);
            if (lane >= d) x += y;
        }
        if (lane == 31) warp_sums[wid] = x;
        __syncthreads();
        if (wid == 0) {
            int tsum = warp_sums[lane];
            #pragma unroll
            for (int d = 1; d < 32; d <<= 1) {
                int y = __shfl_up_sync(0xffffffff, tsum, d);
                if (lane >= d) tsum += y;
            }
            warp_sums[lane] = tsum;
        }
        __syncthreads();
        int warp_off = (wid > 0) ? warp_sums[wid - 1] : 0;
        int excl = s_carry + warp_off + x - v;
        if (i < n) { g_rowptr[i] = excl; g_wofs[i] = excl; }
        __syncthreads();
        if (tid == 0) s_carry += warp_sums[31];
        __syncthreads();
    }
    if (threadIdx.x == 0) g_rowptr[n] = s_carry;
}

// ---------------------------------------------------------------------------
// Kernel 2c: scatter edges into row-sorted order
// ---------------------------------------------------------------------------
__global__ __launch_bounds__(256)
void gcn_scatter_kernel(const int* __restrict__ row,
                        const int* __restrict__ col,
                        const float* __restrict__ val, int E) {
    int e = blockIdx.x * blockDim.x + threadIdx.x;
    if (e >= E) return;
    int r = row[e];
    int p = atomicAdd(&g_wofs[r], 1);
    g_edges[p] = make_int2(col[e], __float_as_int(val[e]));
}

// ---------------------------------------------------------------------------
// Kernel 3: CSR segment reduction over fp16 support (warp per row)
// Lane covers 8 cols (one uint4 = 8 halves per edge). 8-edge unroll for MLP.
// ---------------------------------------------------------------------------
__device__ __forceinline__ void acc_edge(float acc[8], uint4 v, float wv) {
    const __half2* h = (const __half2*)&v;
    #pragma unroll
    for (int p = 0; p < 4; p++) {
        float2 f = __half22float2(h[p]);
        acc[2 * p + 0] = fmaf(wv, f.x, acc[2 * p + 0]);
        acc[2 * p + 1] = fmaf(wv, f.y, acc[2 * p + 1]);
    }
}

__global__ __launch_bounds__(256)
void gcn_csr_kernel(const __half* __restrict__ support,
                    const float* __restrict__ bias,
                    float* __restrict__ out, int N) {
    int w    = (blockIdx.x * blockDim.x + threadIdx.x) >> 5;
    int lane = threadIdx.x & 31;
    if (w >= N) return;

    int s = g_rowptr[w];
    int e = g_rowptr[w + 1];

    float acc[8];
    #pragma unroll
    for (int j = 0; j < 8; j++) acc[j] = 0.0f;

    int i = s;
    for (; i + 8 <= e; i += 8) {
        int2  cv[8];
        uint4 v[8];
        #pragma unroll
        for (int u = 0; u < 8; u++) cv[u] = g_edges[i + u];
        #pragma unroll
        for (int u = 0; u < 8; u++)
            v[u] = __ldg((const uint4*)(support + (size_t)cv[u].x * F_OUT) + lane);
        #pragma unroll
        for (int u = 0; u < 8; u++)
            acc_edge(acc, v[u], __int_as_float(cv[u].y));
    }
    for (; i + 4 <= e; i += 4) {
        int2  cv[4];
        uint4 v[4];
        #pragma unroll
        for (int u = 0; u < 4; u++) cv[u] = g_edges[i + u];
        #pragma unroll
        for (int u = 0; u < 4; u++)
            v[u] = __ldg((const uint4*)(support + (size_t)cv[u].x * F_OUT) + lane);
        #pragma unroll
        for (int u = 0; u < 4; u++)
            acc_edge(acc, v[u], __int_as_float(cv[u].y));
    }
    for (; i < e; i++) {
        int2 cv = g_edges[i];
        uint4 v = __ldg((const uint4*)(support + (size_t)cv.x * F_OUT) + lane);
        acc_edge(acc, v, __int_as_float(cv.y));
    }

    // fused epilogue: round-half-even(x*1000)/1000 + bias; cols lane*8..lane*8+7
    float4 bi0 = __ldg((const float4*)bias + lane * 2);
    float4 bi1 = __ldg((const float4*)bias + lane * 2 + 1);
    float4 o0, o1;
    o0.x = __fdiv_rn(rintf(acc[0] * 1000.0f), 1000.0f) + bi0.x;
    o0.y = __fdiv_rn(rintf(acc[1] * 1000.0f), 1000.0f) + bi0.y;
    o0.z = __fdiv_rn(rintf(acc[2] * 1000.0f), 1000.0f) + bi0.z;
    o0.w = __fdiv_rn(rintf(acc[3] * 1000.0f), 1000.0f) + bi0.w;
    o1.x = __fdiv_rn(rintf(acc[4] * 1000.0f), 1000.0f) + bi1.x;
    o1.y = __fdiv_rn(rintf(acc[5] * 1000.0f), 1000.0f) + bi1.y;
    o1.z = __fdiv_rn(rintf(acc[6] * 1000.0f), 1000.0f) + bi1.z;
    o1.w = __fdiv_rn(rintf(acc[7] * 1000.0f), 1000.0f) + bi1.w;

    float4* dst = (float4*)(out + (size_t)w * F_OUT + lane * 8);
    dst[0] = o0;
    dst[1] = o1;
}

// ---------------------------------------------------------------------------
// Launch — CSR build chain on a side stream (overlaps the GEMM).
// ---------------------------------------------------------------------------
extern "C" void kernel_launch(void* const* d_in, const int* in_sizes, int n_in,
                              void* d_out, int out_size) {
    const float* x        = (const float*)d_in[0];
    const float* weight   = (const float*)d_in[1];
    const float* bias     = (const float*)d_in[2];
    const float* edge_val = (const float*)d_in[3];
    const int*   row      = (const int*)d_in[4];
    const int*   col      = (const int*)d_in[5];
    float*       out      = (float*)d_out;

    const int N = in_sizes[0] / F_IN;
    const int E = in_sizes[3];

    __half* support;
    cudaGetSymbolAddress((void**)&support, g_supportH);
    int* count_ptr;
    cudaGetSymbolAddress((void**)&count_ptr, g_count);

    static cudaStream_t s1 = nullptr;
    static cudaEvent_t ev_fork = nullptr, ev_join = nullptr;
    static bool init_done = false;
    if (!init_done) {
        cudaStreamCreateWithFlags(&s1, cudaStreamNonBlocking);
        cudaEventCreateWithFlags(&ev_fork, cudaEventDisableTiming);
        cudaEventCreateWithFlags(&ev_join, cudaEventDisableTiming);
        init_done = true;
    }

    const int eblocks = (E + 255) / 256;

    // fork: CSR build chain on s1, GEMM on main stream
    cudaEventRecord(ev_fork, 0);
    cudaStreamWaitEvent(s1, ev_fork, 0);

    cudaMemsetAsync(count_ptr, 0, (size_t)N * sizeof(int), s1);
    gcn_hist_kernel<<<eblocks, 256, 0, s1>>>(row, E);
    gcn_scan_kernel<<<1, 1024, 0, s1>>>(N);
    gcn_scatter_kernel<<<eblocks, 256, 0, s1>>>(row, col, edge_val, E);
    cudaEventRecord(ev_join, s1);

    dim3 gemm_grid(F_OUT / 128, (N + 127) / 128);
    gcn_mma_gemm<<<gemm_grid, 256>>>(x, weight, support, N);

    // join: CSR reduce needs both support and sorted edges
    cudaStreamWaitEvent(0, ev_join, 0);
    int csr_blocks = (N * 32 + 255) / 256;
    gcn_csr_kernel<<<csr_blocks, 256>>>(support, bias, out, N);
}

// round 11
// speedup vs baseline: 3.4290x; 1.1021x over previous
#include <cuda_runtime.h>
#include <cuda_fp16.h>
#include <cstdint>

#define F_IN  512
#define F_OUT 256
#define MAX_N 100000
#define MAX_E 3200000

// ---------------- device scratch -------------------------------------------
__device__ __half g_supportH[(size_t)MAX_N * F_OUT];        // X @ W  (fp16, 51 MB)
__device__ int    g_count[MAX_N];
__device__ int    g_rowptr[MAX_N + 1];
__device__ int    g_wofs[MAX_N];
__device__ int2   g_edges[MAX_E];

// ---------------- PTX helpers ----------------------------------------------
__device__ __forceinline__ uint32_t smem_u32(const void* p) {
    uint32_t a;
    asm("{ .reg .u64 t; cvta.to.shared.u64 t, %1; cvt.u32.u64 %0, t; }"
        : "=r"(a) : "l"(p));
    return a;
}

#define LDSM_X4(r0, r1, r2, r3, addr) \
    asm volatile("ldmatrix.sync.aligned.m8n8.x4.shared.b16 {%0,%1,%2,%3}, [%4];" \
                 : "=r"(r0), "=r"(r1), "=r"(r2), "=r"(r3) : "r"(addr))

#define LDSM_X4_T(r0, r1, r2, r3, addr) \
    asm volatile("ldmatrix.sync.aligned.m8n8.x4.trans.shared.b16 {%0,%1,%2,%3}, [%4];" \
                 : "=r"(r0), "=r"(r1), "=r"(r2), "=r"(r3) : "r"(addr))

#define MMA_F16(d0, d1, d2, d3, a0, a1, a2, a3, b0, b1) \
    asm volatile("mma.sync.aligned.m16n8k16.row.col.f32.f16.f16.f32 " \
                 "{%0,%1,%2,%3}, {%4,%5,%6,%7}, {%8,%9}, {%0,%1,%2,%3};" \
                 : "+f"(d0), "+f"(d1), "+f"(d2), "+f"(d3) \
                 : "r"(a0), "r"(a1), "r"(a2), "r"(a3), "r"(b0), "r"(b1))

// split fp32x4 -> (hi f16x4, lo f16x4) packed as uint2 each
__device__ __forceinline__ void split4h(float4 v, uint2& h, uint2& l) {
    __half2 h01 = __floats2half2_rn(v.x, v.y);
    __half2 h23 = __floats2half2_rn(v.z, v.w);
    float2 f01 = __half22float2(h01);
    float2 f23 = __half22float2(h23);
    __half2 l01 = __floats2half2_rn(v.x - f01.x, v.y - f01.y);
    __half2 l23 = __floats2half2_rn(v.z - f23.x, v.w - f23.y);
    h.x = *(uint32_t*)&h01;  h.y = *(uint32_t*)&h23;
    l.x = *(uint32_t*)&l01;  l.y = *(uint32_t*)&l23;
}
__device__ __forceinline__ uint2 pack4h(float4 v) {
    __half2 p01 = __floats2half2_rn(v.x, v.y);
    __half2 p23 = __floats2half2_rn(v.z, v.w);
    uint2 r;
    r.x = *(uint32_t*)&p01;  r.y = *(uint32_t*)&p23;
    return r;
}

// ---------------------------------------------------------------------------
// Kernel 1: 2-term split-fp16 HMMA GEMM over ONE 128-col N-tile.
// support[:, ncol0:ncol0+128] = X @ W[:, ncol0:ncol0+128]
// CTA 128x128, 8 warps (4M x 2N), K-tile 32. 64 MMAs/k-tile.
// ---------------------------------------------------------------------------
#define SA_STR 40
#define SB_STR 136

__global__ __launch_bounds__(256, 2)
void gcn_mma_gemm(const float* __restrict__ A,   // [N, 512]
                  const float* __restrict__ W,   // [512, 256]
                  __half* __restrict__ C,        // [N, 256] fp16
                  int Nn, int ncol0) {
    __shared__ __align__(16) __half sAh[128 * SA_STR];
    __shared__ __align__(16) __half sAl[128 * SA_STR];
    __shared__ __align__(16) __half sB [32 * SB_STR];

    const int tid   = threadIdx.x;
    const int lane  = tid & 31;
    const int wid   = tid >> 5;
    const int warpM = wid & 3;
    const int warpN = wid >> 2;
    const int m0    = blockIdx.y * 128;
    const int n0    = ncol0;

    const uint32_t sAh_b = smem_u32(sAh);
    const uint32_t sAl_b = smem_u32(sAl);
    const uint32_t sB_b  = smem_u32(sB);

    float acc[2][8][4];
    #pragma unroll
    for (int i = 0; i < 2; i++)
        #pragma unroll
        for (int j = 0; j < 8; j++)
            #pragma unroll
            for (int k = 0; k < 4; k++) acc[i][j][k] = 0.0f;

    const int ar = tid >> 1;
    const int ac = (tid & 1) * 16;
    const int kr = tid >> 3;
    const int nc = (tid & 7) * 16;

    const uint32_t a_row  = (uint32_t)(warpM * 32 + (lane & 15));
    const uint32_t a_colb = (uint32_t)((lane >> 4) * 8);
    const uint32_t b_k    = (uint32_t)(((lane >> 3) & 1) * 8 + (lane & 7));
    const uint32_t b_n    = (uint32_t)(warpN * 64 + (lane >> 4) * 8);

    for (int kt = 0; kt < F_IN / 32; kt++) {
        const int k0 = kt * 32;
        {
            const int grow = m0 + ar;
            const float4* ap = (const float4*)(A + (size_t)grow * F_IN + k0 + ac);
            #pragma unroll
            for (int i = 0; i < 4; i++) {
                float4 v = (grow < Nn) ? __ldg(ap + i)
                                       : make_float4(0.f, 0.f, 0.f, 0.f);
                uint2 h, l;
                split4h(v, h, l);
                *(uint2*)(sAh + ar * SA_STR + ac + i * 4) = h;
                *(uint2*)(sAl + ar * SA_STR + ac + i * 4) = l;
            }
            const float4* bp = (const float4*)(W + (size_t)(k0 + kr) * F_OUT + n0 + nc);
            #pragma unroll
            for (int i = 0; i < 4; i++)
                *(uint2*)(sB + kr * SB_STR + nc + i * 4) = pack4h(__ldg(bp + i));
        }
        __syncthreads();

        #pragma unroll
        for (int ks = 0; ks < 2; ks++) {
            const uint32_t aoff0 = (a_row * SA_STR + (uint32_t)(ks * 16) + a_colb) * 2;
            const uint32_t aoff1 = aoff0 + 16 * SA_STR * 2;
            const uint32_t boffk = ((b_k + (uint32_t)(ks * 16)) * SB_STR + b_n) * 2;

            uint32_t ah[8], al[8], b[16];

            LDSM_X4(ah[0], ah[1], ah[2], ah[3], sAh_b + aoff0);
            LDSM_X4(ah[4], ah[5], ah[6], ah[7], sAh_b + aoff1);
            #pragma unroll
            for (int lg = 0; lg < 4; lg++)
                LDSM_X4_T(b[4 * lg], b[4 * lg + 1], b[4 * lg + 2], b[4 * lg + 3],
                          sB_b + boffk + (uint32_t)(lg * 16) * 2);

            #pragma unroll
            for (int mf = 0; mf < 2; mf++)
                #pragma unroll
                for (int nf = 0; nf < 8; nf++)
                    MMA_F16(acc[mf][nf][0], acc[mf][nf][1], acc[mf][nf][2], acc[mf][nf][3],
                            ah[4 * mf], ah[4 * mf + 1], ah[4 * mf + 2], ah[4 * mf + 3],
                            b[2 * nf], b[2 * nf + 1]);

            LDSM_X4(al[0], al[1], al[2], al[3], sAl_b + aoff0);
            LDSM_X4(al[4], al[5], al[6], al[7], sAl_b + aoff1);
            #pragma unroll
            for (int mf = 0; mf < 2; mf++)
                #pragma unroll
                for (int nf = 0; nf < 8; nf++)
                    MMA_F16(acc[mf][nf][0], acc[mf][nf][1], acc[mf][nf][2], acc[mf][nf][3],
                            al[4 * mf], al[4 * mf + 1], al[4 * mf + 2], al[4 * mf + 3],
                            b[2 * nf], b[2 * nf + 1]);
        }
        __syncthreads();
    }

    // ---- epilogue: fp16 stores ----
    const int g  = lane >> 2;
    const int tg = lane & 3;
    #pragma unroll
    for (int mf = 0; mf < 2; mf++) {
        #pragma unroll
        for (int nf = 0; nf < 8; nf++) {
            const int col  = n0 + warpN * 64 + nf * 8 + tg * 2;
            const int row0 = m0 + warpM * 32 + mf * 16 + g;
            const int row1 = row0 + 8;
            if (row0 < Nn)
                *(__half2*)(C + (size_t)row0 * F_OUT + col) =
                    __floats2half2_rn(acc[mf][nf][0], acc[mf][nf][1]);
            if (row1 < Nn)
                *(__half2*)(C + (size_t)row1 * F_OUT + col) =
                    __floats2half2_rn(acc[mf][nf][2], acc[mf][nf][3]);
        }
    }
}

// ---------------------------------------------------------------------------
// Kernel 2a: histogram of destination rows
// ---------------------------------------------------------------------------
__global__ __launch_bounds__(256)
void gcn_hist_kernel(const int* __restrict__ row, int E) {
    int e = blockIdx.x * blockDim.x + threadIdx.x;
    if (e < E) atomicAdd(&g_count[row[e]], 1);
}

// ---------------------------------------------------------------------------
// Kernel 2b: exclusive scan -> rowptr + cursors (single block)
// ---------------------------------------------------------------------------
__global__ __launch_bounds__(1024)
void gcn_scan_kernel(int n) {
    __shared__ int warp_sums[32];
    __shared__ int s_carry;
    const int tid = threadIdx.x, lane = tid & 31, wid = tid >> 5;
    if (tid == 0) s_carry = 0;
    __syncthreads();
    for (int base = 0; base < n; base += 1024) {
        int i = base + tid;
        int v = (i < n) ? g_count[i] : 0;
        int x = v;
        #pragma unroll
        for (int d = 1; d < 32; d <<= 1) {
            int y = __shfl_up_sync(0xffffffff, x, d);
            if (lane >= d) x += y;
        }
        if (lane == 31) warp_sums[wid] = x;
        __syncthreads();
        if (wid == 0) {
            int tsum = warp_sums[lane];
            #pragma unroll
            for (int d = 1; d < 32; d <<= 1) {
                int y = __shfl_up_sync(0xffffffff, tsum, d);
                if (lane >= d) tsum += y;
            }
            warp_sums[lane] = tsum;
        }
        __syncthreads();
        int warp_off = (wid > 0) ? warp_sums[wid - 1] : 0;
        int excl = s_carry + warp_off + x - v;
        if (i < n) { g_rowptr[i] = excl; g_wofs[i] = excl; }
        __syncthreads();
        if (tid == 0) s_carry += warp_sums[31];
        __syncthreads();
    }
    if (threadIdx.x == 0) g_rowptr[n] = s_carry;
}

// ---------------------------------------------------------------------------
// Kernel 2c: scatter edges into row-sorted order
// ---------------------------------------------------------------------------
__global__ __launch_bounds__(256)
void gcn_scatter_kernel(const int* __restrict__ row,
                        const int* __restrict__ col,
                        const float* __restrict__ val, int E) {
    int e = blockIdx.x * blockDim.x + threadIdx.x;
    if (e >= E) return;
    int r = row[e];
    int p = atomicAdd(&g_wofs[r], 1);
    g_edges[p] = make_int2(col[e], __float_as_int(val[e]));
}

// ---------------------------------------------------------------------------
// Kernel 3: CSR segment reduction over ONE 128-col half of fp16 support.
// Warp per row; lane covers 4 cols (uint2 = 4 halves per edge). 8-edge unroll.
// ---------------------------------------------------------------------------
__device__ __forceinline__ void acc_edge2(float acc[4], uint2 v, float wv) {
    const __half2* h = (const __half2*)&v;
    float2 f0 = __half22float2(h[0]);
    float2 f1 = __half22float2(h[1]);
    acc[0] = fmaf(wv, f0.x, acc[0]);
    acc[1] = fmaf(wv, f0.y, acc[1]);
    acc[2] = fmaf(wv, f1.x, acc[2]);
    acc[3] = fmaf(wv, f1.y, acc[3]);
}

__global__ __launch_bounds__(256)
void gcn_csr_kernel(const __half* __restrict__ support,
                    const float* __restrict__ bias,
                    float* __restrict__ out, int N, int coff) {
    int w    = (blockIdx.x * blockDim.x + threadIdx.x) >> 5;
    int lane = threadIdx.x & 31;
    if (w >= N) return;

    int s = g_rowptr[w];
    int e = g_rowptr[w + 1];

    float acc[4] = {0.f, 0.f, 0.f, 0.f};

    int i = s;
    for (; i + 8 <= e; i += 8) {
        int2  cv[8];
        uint2 v[8];
        #pragma unroll
        for (int u = 0; u < 8; u++) cv[u] = g_edges[i + u];
        #pragma unroll
        for (int u = 0; u < 8; u++)
            v[u] = __ldg((const uint2*)(support + (size_t)cv[u].x * F_OUT + coff) + lane);
        #pragma unroll
        for (int u = 0; u < 8; u++)
            acc_edge2(acc, v[u], __int_as_float(cv[u].y));
    }
    for (; i + 4 <= e; i += 4) {
        int2  cv[4];
        uint2 v[4];
        #pragma unroll
        for (int u = 0; u < 4; u++) cv[u] = g_edges[i + u];
        #pragma unroll
        for (int u = 0; u < 4; u++)
            v[u] = __ldg((const uint2*)(support + (size_t)cv[u].x * F_OUT + coff) + lane);
        #pragma unroll
        for (int u = 0; u < 4; u++)
            acc_edge2(acc, v[u], __int_as_float(cv[u].y));
    }
    for (; i < e; i++) {
        int2 cv = g_edges[i];
        uint2 v = __ldg((const uint2*)(support + (size_t)cv.x * F_OUT + coff) + lane);
        acc_edge2(acc, v, __int_as_float(cv.y));
    }

    // fused epilogue: round-half-even(x*1000)/1000 + bias; cols coff+lane*4..+3
    float4 bi = __ldg((const float4*)(bias + coff) + lane);
    float4 o;
    o.x = __fdiv_rn(rintf(acc[0] * 1000.0f), 1000.0f) + bi.x;
    o.y = __fdiv_rn(rintf(acc[1] * 1000.0f), 1000.0f) + bi.y;
    o.z = __fdiv_rn(rintf(acc[2] * 1000.0f), 1000.0f) + bi.z;
    o.w = __fdiv_rn(rintf(acc[3] * 1000.0f), 1000.0f) + bi.w;

    *(float4*)(out + (size_t)w * F_OUT + coff + lane * 4) = o;
}

// ---------------------------------------------------------------------------
// Launch — three-way pipeline:
//   s1: CSR build chain (hidden under GEMM0)
//   main: GEMM(cols 0-127) -> GEMM(cols 128-255) -> CSR(cols 128-255)
//   s2: CSR(cols 0-127), overlapping GEMM(cols 128-255)
// ---------------------------------------------------------------------------
extern "C" void kernel_launch(void* const* d_in, const int* in_sizes, int n_in,
                              void* d_out, int out_size) {
    const float* x        = (const float*)d_in[0];
    const float* weight   = (const float*)d_in[1];
    const float* bias     = (const float*)d_in[2];
    const float* edge_val = (const float*)d_in[3];
    const int*   row      = (const int*)d_in[4];
    const int*   col      = (const int*)d_in[5];
    float*       out      = (float*)d_out;

    const int N = in_sizes[0] / F_IN;
    const int E = in_sizes[3];

    __half* support;
    cudaGetSymbolAddress((void**)&support, g_supportH);
    int* count_ptr;
    cudaGetSymbolAddress((void**)&count_ptr, g_count);

    static cudaStream_t s1 = nullptr, s2 = nullptr;
    static cudaEvent_t ev_fork = nullptr, ev_join = nullptr;
    static cudaEvent_t ev_g0 = nullptr, ev_c0 = nullptr;
    static bool init_done = false;
    if (!init_done) {
        cudaStreamCreateWithFlags(&s1, cudaStreamNonBlocking);
        cudaStreamCreateWithFlags(&s2, cudaStreamNonBlocking);
        cudaEventCreateWithFlags(&ev_fork, cudaEventDisableTiming);
        cudaEventCreateWithFlags(&ev_join, cudaEventDisableTiming);
        cudaEventCreateWithFlags(&ev_g0, cudaEventDisableTiming);
        cudaEventCreateWithFlags(&ev_c0, cudaEventDisableTiming);
        init_done = true;
    }

    const int eblocks   = (E + 255) / 256;
    const int csr_blocks = (N * 32 + 255) / 256;
    const dim3 gemm_grid(1, (N + 127) / 128);

    // fork: CSR build chain on s1
    cudaEventRecord(ev_fork, 0);
    cudaStreamWaitEvent(s1, ev_fork, 0);

    cudaMemsetAsync(count_ptr, 0, (size_t)N * sizeof(int), s1);
    gcn_hist_kernel<<<eblocks, 256, 0, s1>>>(row, E);
    gcn_scan_kernel<<<1, 1024, 0, s1>>>(N);
    gcn_scatter_kernel<<<eblocks, 256, 0, s1>>>(row, col, edge_val, E);
    cudaEventRecord(ev_join, s1);

    // GEMM half 0 (cols 0-127) on main
    gcn_mma_gemm<<<gemm_grid, 256>>>(x, weight, support, N, 0);
    cudaEventRecord(ev_g0, 0);

    // GEMM half 1 (cols 128-255) on main
    gcn_mma_gemm<<<gemm_grid, 256>>>(x, weight, support, N, 128);

    // CSR half 0 on s2: needs GEMM0 + sorted edges; overlaps GEMM1
    cudaStreamWaitEvent(s2, ev_g0, 0);
    cudaStreamWaitEvent(s2, ev_join, 0);
    gcn_csr_kernel<<<csr_blocks, 256, 0, s2>>>(support, bias, out, N, 0);
    cudaEventRecord(ev_c0, s2);

    // CSR half 1 on main: needs GEMM1 (stream order) + sorted edges
    cudaStreamWaitEvent(0, ev_join, 0);
    gcn_csr_kernel<<<csr_blocks, 256>>>(support, bias, out, N, 128);

    // join s2 back into main
    cudaStreamWaitEvent(0, ev_c0, 0);
}